// round 12
// baseline (speedup 1.0000x reference)
#include <cuda_runtime.h>
#include <cuda_bf16.h>
#include <math.h>
#include <stdint.h>

#define NN 50000
#define EE 800000
#define DD 128
#define CAP 64          // bucket capacity per node (Poisson(16): max deg ~45)
#define BN_EPS 1e-5f

// ---------------- scratch (static device globals; no allocation) -------------
// Self-resetting protocol: g_degx and g_cnt start at 0 (BSS zero-init), are
// accumulated by k_build, and are reset by their LAST reader each call
// (g_degx in k_dis, g_cnt in k_agg2).
__device__ float g_degx[NN];
__device__ float g_dis[NN];
__device__ int   g_cnt[NN];
__device__ int   g_src [NN * CAP];      // bucketed source indices
__device__ float g_wr  [NN * CAP];      // bucketed raw edge weights
__device__ float g_h  [NN * DD];        // emb @ W0   (fp32, agg gather operand)
__device__ float g_g  [NN * DD];        // h1 @ W1    (fp32, agg gather operand)
__device__ __nv_bfloat162 g_h1h2[NN * 64];  // h1 split hi (GEMM2 input)
__device__ __nv_bfloat162 g_h1l2[NN * 64];  // h1 split lo
__device__ __nv_bfloat16 g_wh[2 * DD * DD]; // W0,W1 split hi  [sel][k][n]
__device__ __nv_bfloat16 g_wl[2 * DD * DD]; // W0,W1 split lo

// ---------------- small helpers ---------------------------------------------
__device__ __forceinline__ uint32_t smem_u32(const void* p) {
    uint32_t a;
    asm("{ .reg .u64 t; cvta.to.shared.u64 t, %1; cvt.u32.u64 %0, t; }"
        : "=r"(a) : "l"(p));
    return a;
}

__device__ __forceinline__ uint32_t pack_bf16x2(float lo, float hi) {
    __nv_bfloat162 t = __floats2bfloat162_rn(lo, hi);   // .x = lo half
    return *(uint32_t*)&t;
}

#define LDSM4(r0, r1, r2, r3, addr) \
    asm volatile("ldmatrix.sync.aligned.m8n8.x4.shared.b16 {%0,%1,%2,%3}, [%4];" \
                 : "=r"(r0), "=r"(r1), "=r"(r2), "=r"(r3) : "r"(addr))

#define LDSM4T(r0, r1, r2, r3, addr) \
    asm volatile("ldmatrix.sync.aligned.m8n8.x4.trans.shared.b16 {%0,%1,%2,%3}, [%4];" \
                 : "=r"(r0), "=r"(r1), "=r"(r2), "=r"(r3) : "r"(addr))

#define MMA16816(c, a0, a1, a2, a3, b0, b1) \
    asm volatile("mma.sync.aligned.m16n8k16.row.col.f32.bf16.bf16.f32 " \
                 "{%0,%1,%2,%3}, {%4,%5,%6,%7}, {%8,%9}, {%0,%1,%2,%3};" \
                 : "+f"((c)[0]), "+f"((c)[1]), "+f"((c)[2]), "+f"((c)[3]) \
                 : "r"(a0), "r"(a1), "r"(a2), "r"(a3), "r"(b0), "r"(b1))

// split a float4 into hi/lo bf16 pairs and store 8 bytes to each buffer
__device__ __forceinline__ void split_store(__nv_bfloat16* H, __nv_bfloat16* L,
                                            int off, float4 v) {
    float hx = __bfloat162float(__float2bfloat16(v.x));
    float hy = __bfloat162float(__float2bfloat16(v.y));
    float hz = __bfloat162float(__float2bfloat16(v.z));
    float hw = __bfloat162float(__float2bfloat16(v.w));
    uint2 hp = make_uint2(pack_bf16x2(hx, hy), pack_bf16x2(hz, hw));
    uint2 lp = make_uint2(pack_bf16x2(v.x - hx, v.y - hy),
                          pack_bf16x2(v.z - hz, v.w - hw));
    *(uint2*)(H + off) = hp;
    *(uint2*)(L + off) = lp;
}

// ---------------- W split (both layers, one launch) --------------------------
__global__ void k_split_w(const float* __restrict__ W0, const float* __restrict__ W1) {
    int idx = blockIdx.x * 256 + threadIdx.x;       // 0..8191 float4s
    if (idx >= 8192) return;
    const float4* src = (const float4*)((idx < 4096) ? W0 : W1);
    int e4 = idx & 4095;
    float4 v = src[e4];
    int off = ((idx < 4096) ? 0 : (DD * DD)) + e4 * 4;
    split_store(g_wh, g_wl, off, v);
}

// ---------------- CSC build: single edge pass into fixed buckets -------------
__global__ void k_build(const int* __restrict__ row, const int* __restrict__ col,
                        const float* __restrict__ w) {
    int e = blockIdx.x * blockDim.x + threadIdx.x;
    if (e < EE) {
        int c = col[e];
        float we = w[e];
        atomicAdd(&g_degx[c], we);
        int p = atomicAdd(&g_cnt[c], 1);
        if (p < CAP) {
            g_src[c * CAP + p] = row[e];
            g_wr [c * CAP + p] = we;
        }
    }
}

// ---------------- dis = rsqrt(1 + deg); reset deg ----------------------------
__global__ void k_dis() {
    int i = blockIdx.x * blockDim.x + threadIdx.x;
    if (i < NN) {
        g_dis[i] = rsqrtf(1.0f + g_degx[i]);   // +1.0 = self-loop weight
        g_degx[i] = 0.0f;                      // reset for next call
    }
}

// =============== tensor-core GEMM (bf16 3-term split, fused k-loop) ==========
#define PITCH 136                      // bf16 elements per smem row (+8 pad)
#define MAT_BYTES (128 * PITCH * 2)    // 34816
#define SM_TOT (4 * MAT_BYTES)         // 139264

__global__ __launch_bounds__(256) void k_gemm_mma(const float* __restrict__ Af,
                                                  int sel) {
    extern __shared__ __align__(16) char sm[];
    __nv_bfloat16* Ah = (__nv_bfloat16*)(sm);
    __nv_bfloat16* Al = (__nv_bfloat16*)(sm + 1 * MAT_BYTES);
    __nv_bfloat16* Wh = (__nv_bfloat16*)(sm + 2 * MAT_BYTES);
    __nv_bfloat16* Wl = (__nv_bfloat16*)(sm + 3 * MAT_BYTES);

    float* C = (sel == 0) ? g_h : g_g;
    const __nv_bfloat16* WHs = g_wh + sel * (DD * DD);
    const __nv_bfloat16* WLs = g_wl + sel * (DD * DD);

    int tid = threadIdx.x;
    int lane = tid & 31, wid = tid >> 5;
    int rowBase = blockIdx.x * 128;

#pragma unroll
    for (int it = 0; it < 8; it++) {
        int idx = tid + it * 256;            // 0..2047 uint4s
        int k = idx >> 4, n = (idx & 15) * 8;
        uint4 vh = *(const uint4*)(WHs + k * 128 + n);
        uint4 vl = *(const uint4*)(WLs + k * 128 + n);
        *(uint4*)(Wh + k * PITCH + n) = vh;
        *(uint4*)(Wl + k * PITCH + n) = vl;
    }

    if (sel == 0) {
#pragma unroll
        for (int it = 0; it < 16; it++) {
            int idx = tid + it * 256;        // 0..4095 float4s
            int r = idx >> 5, c = (idx & 31) * 4;
            int gr = rowBase + r;
            float4 v = (gr < NN) ? *(const float4*)(Af + (size_t)gr * 128 + c)
                                 : make_float4(0.f, 0.f, 0.f, 0.f);
            split_store(Ah, Al, r * PITCH + c, v);
        }
    } else {
        const uint4 zz = make_uint4(0, 0, 0, 0);
        const uint4* H4 = (const uint4*)g_h1h2;
        const uint4* L4 = (const uint4*)g_h1l2;
#pragma unroll
        for (int it = 0; it < 8; it++) {
            int idx = tid + it * 256;        // 0..2047 uint4s
            int r = idx >> 4, q = idx & 15;  // q = 16-byte chunk (8 bf16)
            int gr = rowBase + r;
            uint4 vh = zz, vl = zz;
            if (gr < NN) {
                vh = H4[(size_t)gr * 16 + q];
                vl = L4[(size_t)gr * 16 + q];
            }
            *(uint4*)(Ah + r * PITCH + q * 8) = vh;
            *(uint4*)(Al + r * PITCH + q * 8) = vl;
        }
    }
    __syncthreads();

    int m0 = (wid & 3) * 32;
    int n0 = (wid >> 2) * 64;

    float acc[2][8][4];
#pragma unroll
    for (int mt = 0; mt < 2; mt++)
#pragma unroll
        for (int j = 0; j < 8; j++)
#pragma unroll
            for (int q = 0; q < 4; q++) acc[mt][j][q] = 0.f;

    uint32_t AhB = smem_u32(Ah), AlB = smem_u32(Al);
    uint32_t WhB = smem_u32(Wh), WlB = smem_u32(Wl);
    int a_r = lane & 15, a_c8 = (lane >> 4) << 3;
    int b_k = lane & 15, b_n8 = (lane >> 4) << 3;

#pragma unroll
    for (int ks = 0; ks < 8; ks++) {
        int k0 = ks * 16;
        uint32_t ah[2][4], al[2][4];
#pragma unroll
        for (int mt = 0; mt < 2; mt++) {
            uint32_t aoff = (uint32_t)((m0 + mt * 16 + a_r) * PITCH + k0 + a_c8) * 2;
            LDSM4(ah[mt][0], ah[mt][1], ah[mt][2], ah[mt][3], AhB + aoff);
            LDSM4(al[mt][0], al[mt][1], al[mt][2], al[mt][3], AlB + aoff);
        }
#pragma unroll
        for (int nt = 0; nt < 4; nt++) {
            uint32_t boff = (uint32_t)((k0 + b_k) * PITCH + n0 + nt * 16 + b_n8) * 2;
            uint32_t bh0, bh1, bh2, bh3, bl0, bl1, bl2, bl3;
            LDSM4T(bh0, bh1, bh2, bh3, WhB + boff);
            LDSM4T(bl0, bl1, bl2, bl3, WlB + boff);
#pragma unroll
            for (int mt = 0; mt < 2; mt++) {
                MMA16816(acc[mt][2 * nt],     ah[mt][0], ah[mt][1], ah[mt][2], ah[mt][3], bh0, bh1);
                MMA16816(acc[mt][2 * nt + 1], ah[mt][0], ah[mt][1], ah[mt][2], ah[mt][3], bh2, bh3);
                MMA16816(acc[mt][2 * nt],     ah[mt][0], ah[mt][1], ah[mt][2], ah[mt][3], bl0, bl1);
                MMA16816(acc[mt][2 * nt + 1], ah[mt][0], ah[mt][1], ah[mt][2], ah[mt][3], bl2, bl3);
                MMA16816(acc[mt][2 * nt],     al[mt][0], al[mt][1], al[mt][2], al[mt][3], bh0, bh1);
                MMA16816(acc[mt][2 * nt + 1], al[mt][0], al[mt][1], al[mt][2], al[mt][3], bh2, bh3);
            }
        }
    }

    int rr = lane >> 2, cc = (lane & 3) * 2;
#pragma unroll
    for (int mt = 0; mt < 2; mt++) {
        int r0 = rowBase + m0 + mt * 16 + rr;
        bool v0 = r0 < NN, v1 = (r0 + 8) < NN;
#pragma unroll
        for (int j = 0; j < 8; j++) {
            int n = n0 + j * 8 + cc;
            if (v0) *(float2*)(C + (size_t)r0 * 128 + n)
                        = make_float2(acc[mt][j][0], acc[mt][j][1]);
            if (v1) *(float2*)(C + (size_t)(r0 + 8) * 128 + n)
                        = make_float2(acc[mt][j][2], acc[mt][j][3]);
        }
    }
}

// ======= aggregation core: ONE WARP per node, float4 lanes, unroll 4 =========
// Computes dis_i * ( sum_e dis_src*w*h_src + dis_i*h_i )  (norm factorized).
__device__ __forceinline__ float4 agg_gather_w(const float* __restrict__ H,
                                               int i, int lane) {
    const float4* H4 = (const float4*)H;
    float di = g_dis[i];
    float4 sv = H4[(size_t)i * 32 + lane];
    float4 a0 = make_float4(di * sv.x, di * sv.y, di * sv.z, di * sv.w);
    float4 a1 = make_float4(0.f, 0.f, 0.f, 0.f);
    float4 a2 = a1, a3 = a1;

    int s = i * CAP;
    int n = g_cnt[i];
    n = (n < CAP) ? n : CAP;

    for (int p = 0; p < n; p += 4) {
        bool u1 = p + 1 < n, u2 = p + 2 < n, u3 = p + 3 < n;
        int   i0 = g_src[s + p];
        int   i1 = u1 ? g_src[s + p + 1] : 0;
        int   i2 = u2 ? g_src[s + p + 2] : 0;
        int   i3 = u3 ? g_src[s + p + 3] : 0;
        float w0 = g_dis[i0] * g_wr[s + p];
        float w1 = u1 ? g_dis[i1] * g_wr[s + p + 1] : 0.f;
        float w2 = u2 ? g_dis[i2] * g_wr[s + p + 2] : 0.f;
        float w3 = u3 ? g_dis[i3] * g_wr[s + p + 3] : 0.f;

        float4 h0 = H4[(size_t)i0 * 32 + lane];
        float4 h1 = H4[(size_t)i1 * 32 + lane];
        float4 h2 = H4[(size_t)i2 * 32 + lane];
        float4 h3 = H4[(size_t)i3 * 32 + lane];

        a0.x += w0 * h0.x; a0.y += w0 * h0.y; a0.z += w0 * h0.z; a0.w += w0 * h0.w;
        a1.x += w1 * h1.x; a1.y += w1 * h1.y; a1.z += w1 * h1.z; a1.w += w1 * h1.w;
        a2.x += w2 * h2.x; a2.y += w2 * h2.y; a2.z += w2 * h2.z; a2.w += w2 * h2.w;
        a3.x += w3 * h3.x; a3.y += w3 * h3.y; a3.z += w3 * h3.z; a3.w += w3 * h3.w;
    }
    return make_float4(di * ((a0.x + a1.x) + (a2.x + a3.x)),
                       di * ((a0.y + a1.y) + (a2.y + a3.y)),
                       di * ((a0.z + a1.z) + (a2.z + a3.z)),
                       di * ((a0.w + a1.w) + (a2.w + a3.w)));
}

// ---------------- aggregation 1: conv1 + bias + BN + ELU -> bf16 split -------
__global__ __launch_bounds__(256) void k_agg1(const float* __restrict__ b0,
                       const float* __restrict__ gamma,
                       const float* __restrict__ beta,
                       const float* __restrict__ mean,
                       const float* __restrict__ var) {
    int lane = threadIdx.x & 31;
    int i = blockIdx.x * 8 + (threadIdx.x >> 5);   // 6250 * 8 = 50000 exact

    float4 acc = agg_gather_w(g_h, i, lane);

    float4 bb = *(const float4*)(b0    + 4 * lane);
    float4 gm = *(const float4*)(gamma + 4 * lane);
    float4 bt = *(const float4*)(beta  + 4 * lane);
    float4 mn = *(const float4*)(mean  + 4 * lane);
    float4 vr = *(const float4*)(var   + 4 * lane);

    float y0 = (acc.x + bb.x - mn.x) * (gm.x * rsqrtf(vr.x + BN_EPS)) + bt.x;
    float y1 = (acc.y + bb.y - mn.y) * (gm.y * rsqrtf(vr.y + BN_EPS)) + bt.y;
    float y2 = (acc.z + bb.z - mn.z) * (gm.z * rsqrtf(vr.z + BN_EPS)) + bt.z;
    float y3 = (acc.w + bb.w - mn.w) * (gm.w * rsqrtf(vr.w + BN_EPS)) + bt.w;
    y0 = (y0 > 0.f) ? y0 : expm1f(y0);
    y1 = (y1 > 0.f) ? y1 : expm1f(y1);
    y2 = (y2 > 0.f) ? y2 : expm1f(y2);
    y3 = (y3 > 0.f) ? y3 : expm1f(y3);

    float h0 = __bfloat162float(__float2bfloat16(y0));
    float h1 = __bfloat162float(__float2bfloat16(y1));
    float h2 = __bfloat162float(__float2bfloat16(y2));
    float h3 = __bfloat162float(__float2bfloat16(y3));

    size_t o = (size_t)i * 64 + 2 * lane;   // bf162 index
    g_h1h2[o]     = __floats2bfloat162_rn(h0, h1);
    g_h1h2[o + 1] = __floats2bfloat162_rn(h2, h3);
    g_h1l2[o]     = __floats2bfloat162_rn(y0 - h0, y1 - h1);
    g_h1l2[o + 1] = __floats2bfloat162_rn(y2 - h2, y3 - h3);
}

// ---------------- aggregation 2 + final fusion mean; resets g_cnt ------------
__global__ __launch_bounds__(256) void k_agg2(const float* __restrict__ emb,
                       const float* __restrict__ b1,
                       float* __restrict__ out) {
    int lane = threadIdx.x & 31;
    int i = blockIdx.x * 8 + (threadIdx.x >> 5);

    float4 acc = agg_gather_w(g_g, i, lane);
    if (lane == 0) g_cnt[i] = 0;     // last reader resets for next call

    float4 bb = *(const float4*)(b1 + 4 * lane);
    size_t o = (size_t)i * 128 + 4 * lane;
    float4 em = *(const float4*)(emb + o);

    size_t o2 = (size_t)i * 64 + 2 * lane;
    __nv_bfloat162 ha = g_h1h2[o2], hb = g_h1h2[o2 + 1];
    __nv_bfloat162 la = g_h1l2[o2], lb = g_h1l2[o2 + 1];
    float h1x = __bfloat162float(ha.x) + __bfloat162float(la.x);
    float h1y = __bfloat162float(ha.y) + __bfloat162float(la.y);
    float h1z = __bfloat162float(hb.x) + __bfloat162float(lb.x);
    float h1w = __bfloat162float(hb.y) + __bfloat162float(lb.y);

    float4 r;
    r.x = (em.x + h1x + acc.x + bb.x) * (1.0f / 3.0f);
    r.y = (em.y + h1y + acc.y + bb.y) * (1.0f / 3.0f);
    r.z = (em.z + h1z + acc.z + bb.z) * (1.0f / 3.0f);
    r.w = (em.w + h1w + acc.w + bb.w) * (1.0f / 3.0f);
    *(float4*)(out + o) = r;
}

// ---------------- launch: fork/join so GEMM1 overlaps graph prep -------------
extern "C" void kernel_launch(void* const* d_in, const int* in_sizes, int n_in,
                              void* d_out, int out_size) {
    const float* emb   = (const float*)d_in[0];
    const int*   ei    = (const int*)  d_in[1];
    const float* ew    = (const float*)d_in[2];
    const float* W0    = (const float*)d_in[3];
    const float* b0    = (const float*)d_in[4];
    const float* W1    = (const float*)d_in[5];
    const float* b1    = (const float*)d_in[6];
    const float* gamma = (const float*)d_in[7];
    const float* beta  = (const float*)d_in[8];
    const float* mean  = (const float*)d_in[9];
    const float* var   = (const float*)d_in[10];
    float* out = (float*)d_out;

    const int* row = ei;        // edge_index[0]
    const int* col = ei + EE;   // edge_index[1]

    const int NB_E = (EE + 255) / 256;
    const int NB_N = (NN + 255) / 256;
    const int NTILE = (NN + 127) / 128;   // 391

    // one-time handles (no device memory; identical work every call)
    static cudaStream_t s_side = ([]() {
        cudaStream_t t;
        cudaStreamCreateWithFlags(&t, cudaStreamNonBlocking);
        return t;
    })();
    static cudaEvent_t s_fork = ([]() {
        cudaEvent_t e;
        cudaEventCreateWithFlags(&e, cudaEventDisableTiming);
        return e;
    })();
    static cudaEvent_t s_join = ([]() {
        cudaEvent_t e;
        cudaEventCreateWithFlags(&e, cudaEventDisableTiming);
        return e;
    })();
    static bool s_attr = ([]() {
        cudaFuncSetAttribute(k_gemm_mma,
                             cudaFuncAttributeMaxDynamicSharedMemorySize, SM_TOT);
        return true;
    })();
    (void)s_attr;

    // fork: side branch = W split + GEMM1 (independent of graph prep)
    cudaEventRecord(s_fork, 0);
    cudaStreamWaitEvent(s_side, s_fork, 0);
    k_split_w<<<32, 256, 0, s_side>>>(W0, W1);
    k_gemm_mma<<<NTILE, 256, SM_TOT, s_side>>>(emb, 0);   // g_h = emb @ W0
    cudaEventRecord(s_join, s_side);

    // main branch: single-pass bucket CSC build + dis
    k_build<<<NB_E, 256>>>(row, col, ew);
    k_dis  <<<NB_N, 256>>>();

    // join, then the dependent tail
    cudaStreamWaitEvent(0, s_join, 0);
    k_agg1<<<NN / 8, 256>>>(b0, gamma, beta, mean, var);
    k_gemm_mma<<<NTILE, 256, SM_TOT>>>(nullptr, 1);       // g_g = h1 @ W1
    k_agg2<<<NN / 8, 256>>>(emb, b1, out);
}

// round 13
// speedup vs baseline: 1.0580x; 1.0580x over previous
#include <cuda_runtime.h>
#include <cuda_bf16.h>
#include <cuda_fp16.h>
#include <math.h>
#include <stdint.h>

#define NN 50000
#define EE 800000
#define DD 128
#define BN_EPS 1e-5f
#define NSCAN_BLK 196   // ceil(50000/256)
#define NHALF 25088     // agg1/gemm2 pipeline split (196 tiles * 128)

// ---------------- scratch (static device globals; no allocation) -------------
// Self-resetting protocol: g_degx and g_cnt start at 0 (BSS zero-init), are
// accumulated by k_deg, and are reset to 0 by their LAST reader each call.
__device__ float g_degx[NN];
__device__ float g_dis[NN];
__device__ int   g_cnt[NN];
__device__ int   g_off[NN];
__device__ int   g_cur[NN];
__device__ int   g_bsum[256];
__device__ int   g_src[EE];
__device__ float g_wn [EE];
__device__ __half2 g_h2[NN * 64];       // emb @ W0   (fp16, agg gather operand)
__device__ __half2 g_g2[NN * 64];       // h1 @ W1    (fp16, agg gather operand)
__device__ __nv_bfloat162 g_h1h2[NN * 64];  // h1 split hi (GEMM2 input)
__device__ __nv_bfloat162 g_h1l2[NN * 64];  // h1 split lo
__device__ __nv_bfloat16 g_wh[2 * DD * DD]; // W0,W1 split hi  [sel][k][n]
__device__ __nv_bfloat16 g_wl[2 * DD * DD]; // W0,W1 split lo

// ---------------- small helpers ---------------------------------------------
__device__ __forceinline__ uint32_t smem_u32(const void* p) {
    uint32_t a;
    asm("{ .reg .u64 t; cvta.to.shared.u64 t, %1; cvt.u32.u64 %0, t; }"
        : "=r"(a) : "l"(p));
    return a;
}

__device__ __forceinline__ uint32_t pack_bf16x2(float lo, float hi) {
    __nv_bfloat162 t = __floats2bfloat162_rn(lo, hi);   // .x = lo half
    return *(uint32_t*)&t;
}

#define LDSM4(r0, r1, r2, r3, addr) \
    asm volatile("ldmatrix.sync.aligned.m8n8.x4.shared.b16 {%0,%1,%2,%3}, [%4];" \
                 : "=r"(r0), "=r"(r1), "=r"(r2), "=r"(r3) : "r"(addr))

#define LDSM4T(r0, r1, r2, r3, addr) \
    asm volatile("ldmatrix.sync.aligned.m8n8.x4.trans.shared.b16 {%0,%1,%2,%3}, [%4];" \
                 : "=r"(r0), "=r"(r1), "=r"(r2), "=r"(r3) : "r"(addr))

#define MMA16816(c, a0, a1, a2, a3, b0, b1) \
    asm volatile("mma.sync.aligned.m16n8k16.row.col.f32.bf16.bf16.f32 " \
                 "{%0,%1,%2,%3}, {%4,%5,%6,%7}, {%8,%9}, {%0,%1,%2,%3};" \
                 : "+f"((c)[0]), "+f"((c)[1]), "+f"((c)[2]), "+f"((c)[3]) \
                 : "r"(a0), "r"(a1), "r"(a2), "r"(a3), "r"(b0), "r"(b1))

// split a float4 into hi/lo bf16 pairs and store 8 bytes to each buffer
__device__ __forceinline__ void split_store(__nv_bfloat16* H, __nv_bfloat16* L,
                                            int off, float4 v) {
    float hx = __bfloat162float(__float2bfloat16(v.x));
    float hy = __bfloat162float(__float2bfloat16(v.y));
    float hz = __bfloat162float(__float2bfloat16(v.z));
    float hw = __bfloat162float(__float2bfloat16(v.w));
    uint2 hp = make_uint2(pack_bf16x2(hx, hy), pack_bf16x2(hz, hw));
    uint2 lp = make_uint2(pack_bf16x2(v.x - hx, v.y - hy),
                          pack_bf16x2(v.z - hz, v.w - hw));
    *(uint2*)(H + off) = hp;
    *(uint2*)(L + off) = lp;
}

// ---------------- W split (both layers, one launch) --------------------------
__global__ void k_split_w(const float* __restrict__ W0, const float* __restrict__ W1) {
    int idx = blockIdx.x * 256 + threadIdx.x;       // 0..8191 float4s
    if (idx >= 8192) return;
    const float4* src = (const float4*)((idx < 4096) ? W0 : W1);
    int e4 = idx & 4095;
    float4 v = src[e4];
    int off = ((idx < 4096) ? 0 : (DD * DD)) + e4 * 4;
    split_store(g_wh, g_wl, off, v);
}

// ---------------- norm + CSC build ------------------------------------------
__global__ void k_deg(const int* __restrict__ col, const float* __restrict__ w) {
    int e = blockIdx.x * blockDim.x + threadIdx.x;
    if (e < EE) {
        int c = col[e];
        atomicAdd(&g_degx[c], w[e]);
        atomicAdd(&g_cnt[c], 1);
    }
}

// per-block sum of counts (scan level 1) + fused deg^-1/2 + g_degx reset
__global__ void k_bsum() {
    int i = blockIdx.x * 256 + threadIdx.x;
    int v = (i < NN) ? g_cnt[i] : 0;
    if (i < NN) {
        g_dis[i] = rsqrtf(1.0f + g_degx[i]);   // +1.0 = self-loop weight
        g_degx[i] = 0.0f;                      // reset for next call
    }

#pragma unroll
    for (int o = 16; o > 0; o >>= 1) v += __shfl_down_sync(0xffffffffu, v, o);
    __shared__ int ws[8];
    int lane = threadIdx.x & 31, wid = threadIdx.x >> 5;
    if (lane == 0) ws[wid] = v;
    __syncthreads();
    if (threadIdx.x < 8) {
        int s = ws[threadIdx.x];
#pragma unroll
        for (int o = 4; o > 0; o >>= 1) s += __shfl_down_sync(0xffu, s, o);
        if (threadIdx.x == 0) g_bsum[blockIdx.x] = s;
    }
}

// scan level 2+3 fused: every block redundantly scans the 196 block sums in
// shared memory (cheap), then does its local scan; resets g_cnt.
__global__ void k_scan3() {
    __shared__ int bs[256];
    int t = threadIdx.x;
    bs[t] = (t < NSCAN_BLK) ? g_bsum[t] : 0;
    __syncthreads();
#pragma unroll
    for (int d = 1; d < 256; d <<= 1) {
        int u = (t >= d) ? bs[t - d] : 0;
        __syncthreads();
        bs[t] += u;
        __syncthreads();
    }
    int blk_base = (blockIdx.x == 0) ? 0 : bs[blockIdx.x - 1];

    int i = blockIdx.x * 256 + t;
    int v = (i < NN) ? g_cnt[i] : 0;
    int lane = t & 31, wid = t >> 5;

    int x = v;
#pragma unroll
    for (int o = 1; o < 32; o <<= 1) {
        int y = __shfl_up_sync(0xffffffffu, x, o);
        if (lane >= o) x += y;
    }
    __shared__ int wsum[8];
    if (lane == 31) wsum[wid] = x;
    __syncthreads();
    if (t < 8) {
        int s = wsum[t];
#pragma unroll
        for (int o = 1; o < 8; o <<= 1) {
            int y = __shfl_up_sync(0xffu, s, o);
            if (t >= o) s += y;
        }
        wsum[t] = s;
    }
    __syncthreads();
    int base = blk_base + ((wid > 0) ? wsum[wid - 1] : 0);
    int excl = base + x - v;
    if (i < NN) {
        g_off[i] = excl;
        g_cur[i] = excl;
        g_cnt[i] = 0;      // reset for next call (last reader)
    }
}

__global__ void k_scatter(const int* __restrict__ row, const int* __restrict__ col,
                          const float* __restrict__ w) {
    int e = blockIdx.x * blockDim.x + threadIdx.x;
    if (e < EE) {
        int r = row[e], c = col[e];
        int p = atomicAdd(&g_cur[c], 1);
        g_src[p] = r;
        g_wn[p]  = g_dis[r] * w[e] * g_dis[c];
    }
}

// =============== tensor-core GEMM (bf16 3-term split, fused k-loop) ==========
#define PITCH 136                      // bf16 elements per smem row (+8 pad)
#define MAT_BYTES (128 * PITCH * 2)    // 34816
#define SM_TOT (4 * MAT_BYTES)         // 139264

__global__ __launch_bounds__(256) void k_gemm_mma(const float* __restrict__ Af,
                                                  int sel, int tile_off) {
    extern __shared__ __align__(16) char sm[];
    __nv_bfloat16* Ah = (__nv_bfloat16*)(sm);
    __nv_bfloat16* Al = (__nv_bfloat16*)(sm + 1 * MAT_BYTES);
    __nv_bfloat16* Wh = (__nv_bfloat16*)(sm + 2 * MAT_BYTES);
    __nv_bfloat16* Wl = (__nv_bfloat16*)(sm + 3 * MAT_BYTES);

    __half2* C2 = (sel == 0) ? g_h2 : g_g2;
    const __nv_bfloat16* WHs = g_wh + sel * (DD * DD);
    const __nv_bfloat16* WLs = g_wl + sel * (DD * DD);

    int tid = threadIdx.x;
    int lane = tid & 31, wid = tid >> 5;
    int rowBase = (tile_off + blockIdx.x) * 128;

#pragma unroll
    for (int it = 0; it < 8; it++) {
        int idx = tid + it * 256;            // 0..2047 uint4s
        int k = idx >> 4, n = (idx & 15) * 8;
        uint4 vh = *(const uint4*)(WHs + k * 128 + n);
        uint4 vl = *(const uint4*)(WLs + k * 128 + n);
        *(uint4*)(Wh + k * PITCH + n) = vh;
        *(uint4*)(Wl + k * PITCH + n) = vl;
    }

    if (sel == 0) {
#pragma unroll
        for (int it = 0; it < 16; it++) {
            int idx = tid + it * 256;        // 0..4095 float4s
            int r = idx >> 5, c = (idx & 31) * 4;
            int gr = rowBase + r;
            float4 v = (gr < NN) ? *(const float4*)(Af + (size_t)gr * 128 + c)
                                 : make_float4(0.f, 0.f, 0.f, 0.f);
            split_store(Ah, Al, r * PITCH + c, v);
        }
    } else {
        const uint4 zz = make_uint4(0, 0, 0, 0);
        const uint4* H4 = (const uint4*)g_h1h2;
        const uint4* L4 = (const uint4*)g_h1l2;
#pragma unroll
        for (int it = 0; it < 8; it++) {
            int idx = tid + it * 256;        // 0..2047 uint4s
            int r = idx >> 4, q = idx & 15;  // q = 16-byte chunk (8 bf16)
            int gr = rowBase + r;
            uint4 vh = zz, vl = zz;
            if (gr < NN) {
                vh = H4[(size_t)gr * 16 + q];
                vl = L4[(size_t)gr * 16 + q];
            }
            *(uint4*)(Ah + r * PITCH + q * 8) = vh;
            *(uint4*)(Al + r * PITCH + q * 8) = vl;
        }
    }
    __syncthreads();

    int m0 = (wid & 3) * 32;
    int n0 = (wid >> 2) * 64;

    float acc[2][8][4];
#pragma unroll
    for (int mt = 0; mt < 2; mt++)
#pragma unroll
        for (int j = 0; j < 8; j++)
#pragma unroll
            for (int q = 0; q < 4; q++) acc[mt][j][q] = 0.f;

    uint32_t AhB = smem_u32(Ah), AlB = smem_u32(Al);
    uint32_t WhB = smem_u32(Wh), WlB = smem_u32(Wl);
    int a_r = lane & 15, a_c8 = (lane >> 4) << 3;
    int b_k = lane & 15, b_n8 = (lane >> 4) << 3;

#pragma unroll
    for (int ks = 0; ks < 8; ks++) {
        int k0 = ks * 16;
        uint32_t ah[2][4], al[2][4];
#pragma unroll
        for (int mt = 0; mt < 2; mt++) {
            uint32_t aoff = (uint32_t)((m0 + mt * 16 + a_r) * PITCH + k0 + a_c8) * 2;
            LDSM4(ah[mt][0], ah[mt][1], ah[mt][2], ah[mt][3], AhB + aoff);
            LDSM4(al[mt][0], al[mt][1], al[mt][2], al[mt][3], AlB + aoff);
        }
#pragma unroll
        for (int nt = 0; nt < 4; nt++) {
            uint32_t boff = (uint32_t)((k0 + b_k) * PITCH + n0 + nt * 16 + b_n8) * 2;
            uint32_t bh0, bh1, bh2, bh3, bl0, bl1, bl2, bl3;
            LDSM4T(bh0, bh1, bh2, bh3, WhB + boff);
            LDSM4T(bl0, bl1, bl2, bl3, WlB + boff);
#pragma unroll
            for (int mt = 0; mt < 2; mt++) {
                MMA16816(acc[mt][2 * nt],     ah[mt][0], ah[mt][1], ah[mt][2], ah[mt][3], bh0, bh1);
                MMA16816(acc[mt][2 * nt + 1], ah[mt][0], ah[mt][1], ah[mt][2], ah[mt][3], bh2, bh3);
                MMA16816(acc[mt][2 * nt],     ah[mt][0], ah[mt][1], ah[mt][2], ah[mt][3], bl0, bl1);
                MMA16816(acc[mt][2 * nt + 1], ah[mt][0], ah[mt][1], ah[mt][2], ah[mt][3], bl2, bl3);
                MMA16816(acc[mt][2 * nt],     al[mt][0], al[mt][1], al[mt][2], al[mt][3], bh0, bh1);
                MMA16816(acc[mt][2 * nt + 1], al[mt][0], al[mt][1], al[mt][2], al[mt][3], bh2, bh3);
            }
        }
    }

    // ---- epilogue: native __half2 stores (cc even -> n0+j*8+cc even)
    int rr = lane >> 2, cc = (lane & 3) * 2;
#pragma unroll
    for (int mt = 0; mt < 2; mt++) {
        int r0 = rowBase + m0 + mt * 16 + rr;
        bool v0 = r0 < NN, v1 = (r0 + 8) < NN;
#pragma unroll
        for (int j = 0; j < 8; j++) {
            int n2 = (n0 + j * 8 + cc) >> 1;
            if (v0) C2[(size_t)r0 * 64 + n2]
                        = __floats2half2_rn(acc[mt][j][0], acc[mt][j][1]);
            if (v1) C2[(size_t)(r0 + 8) * 64 + n2]
                        = __floats2half2_rn(acc[mt][j][2], acc[mt][j][3]);
        }
    }
}

// ======= aggregation core: ONE WARP per node, half2 lanes, unroll 8 ==========
// lane owns features [4*lane, 4*lane+4) = half2 elements {2*lane, 2*lane+1}.
__device__ __forceinline__ float4 agg_gather_w(const __half2* __restrict__ H2,
                                               int i, int lane) {
    float di = g_dis[i];
    float sw = di * di;
    size_t sb = (size_t)i * 64 + 2 * lane;
    float2 sa = __half22float2(H2[sb]);
    float2 sc = __half22float2(H2[sb + 1]);
    float4 a0 = make_float4(sw * sa.x, sw * sa.y, sw * sc.x, sw * sc.y);
    float4 a1 = make_float4(0.f, 0.f, 0.f, 0.f);
    float4 a2 = a1, a3 = a1;

    int s = g_off[i];
    int n = ((i + 1 < NN) ? g_off[i + 1] : EE) - s;

    for (int p = 0; p < n; p += 8) {
        bool u1 = p + 1 < n, u2 = p + 2 < n, u3 = p + 3 < n;
        bool u4 = p + 4 < n, u5 = p + 5 < n, u6 = p + 6 < n, u7 = p + 7 < n;
        int   i0 = g_src[s + p];
        float w0 = g_wn[s + p];
        int   i1 = u1 ? g_src[s + p + 1] : 0;
        float w1 = u1 ? g_wn[s + p + 1] : 0.f;
        int   i2 = u2 ? g_src[s + p + 2] : 0;
        float w2 = u2 ? g_wn[s + p + 2] : 0.f;
        int   i3 = u3 ? g_src[s + p + 3] : 0;
        float w3 = u3 ? g_wn[s + p + 3] : 0.f;
        int   i4 = u4 ? g_src[s + p + 4] : 0;
        float w4 = u4 ? g_wn[s + p + 4] : 0.f;
        int   i5 = u5 ? g_src[s + p + 5] : 0;
        float w5 = u5 ? g_wn[s + p + 5] : 0.f;
        int   i6 = u6 ? g_src[s + p + 6] : 0;
        float w6 = u6 ? g_wn[s + p + 6] : 0.f;
        int   i7 = u7 ? g_src[s + p + 7] : 0;
        float w7 = u7 ? g_wn[s + p + 7] : 0.f;

        size_t b0 = (size_t)i0 * 64 + 2 * lane;
        size_t b1 = (size_t)i1 * 64 + 2 * lane;
        size_t b2 = (size_t)i2 * 64 + 2 * lane;
        size_t b3 = (size_t)i3 * 64 + 2 * lane;
        size_t b4 = (size_t)i4 * 64 + 2 * lane;
        size_t b5 = (size_t)i5 * 64 + 2 * lane;
        size_t b6 = (size_t)i6 * 64 + 2 * lane;
        size_t b7 = (size_t)i7 * 64 + 2 * lane;
        float2 h0a = __half22float2(H2[b0]), h0b = __half22float2(H2[b0 + 1]);
        float2 h1a = __half22float2(H2[b1]), h1b = __half22float2(H2[b1 + 1]);
        float2 h2a = __half22float2(H2[b2]), h2b = __half22float2(H2[b2 + 1]);
        float2 h3a = __half22float2(H2[b3]), h3b = __half22float2(H2[b3 + 1]);
        float2 h4a = __half22float2(H2[b4]), h4b = __half22float2(H2[b4 + 1]);
        float2 h5a = __half22float2(H2[b5]), h5b = __half22float2(H2[b5 + 1]);
        float2 h6a = __half22float2(H2[b6]), h6b = __half22float2(H2[b6 + 1]);
        float2 h7a = __half22float2(H2[b7]), h7b = __half22float2(H2[b7 + 1]);

        a0.x += w0 * h0a.x; a0.y += w0 * h0a.y; a0.z += w0 * h0b.x; a0.w += w0 * h0b.y;
        a1.x += w1 * h1a.x; a1.y += w1 * h1a.y; a1.z += w1 * h1b.x; a1.w += w1 * h1b.y;
        a2.x += w2 * h2a.x; a2.y += w2 * h2a.y; a2.z += w2 * h2b.x; a2.w += w2 * h2b.y;
        a3.x += w3 * h3a.x; a3.y += w3 * h3a.y; a3.z += w3 * h3b.x; a3.w += w3 * h3b.y;
        a0.x += w4 * h4a.x; a0.y += w4 * h4a.y; a0.z += w4 * h4b.x; a0.w += w4 * h4b.y;
        a1.x += w5 * h5a.x; a1.y += w5 * h5a.y; a1.z += w5 * h5b.x; a1.w += w5 * h5b.y;
        a2.x += w6 * h6a.x; a2.y += w6 * h6a.y; a2.z += w6 * h6b.x; a2.w += w6 * h6b.y;
        a3.x += w7 * h7a.x; a3.y += w7 * h7a.y; a3.z += w7 * h7b.x; a3.w += w7 * h7b.y;
    }
    return make_float4((a0.x + a1.x) + (a2.x + a3.x),
                       (a0.y + a1.y) + (a2.y + a3.y),
                       (a0.z + a1.z) + (a2.z + a3.z),
                       (a0.w + a1.w) + (a2.w + a3.w));
}

// ---------------- aggregation 1: conv1 + bias + BN + ELU -> bf16 split -------
__global__ __launch_bounds__(256) void k_agg1(const float* __restrict__ b0,
                       const float* __restrict__ gamma,
                       const float* __restrict__ beta,
                       const float* __restrict__ mean,
                       const float* __restrict__ var,
                       int node_off) {
    int lane = threadIdx.x & 31;
    int i = node_off + blockIdx.x * 8 + (threadIdx.x >> 5);

    float4 acc = agg_gather_w(g_h2, i, lane);

    float4 bb = *(const float4*)(b0    + 4 * lane);
    float4 gm = *(const float4*)(gamma + 4 * lane);
    float4 bt = *(const float4*)(beta  + 4 * lane);
    float4 mn = *(const float4*)(mean  + 4 * lane);
    float4 vr = *(const float4*)(var   + 4 * lane);

    float y0 = (acc.x + bb.x - mn.x) * (gm.x * rsqrtf(vr.x + BN_EPS)) + bt.x;
    float y1 = (acc.y + bb.y - mn.y) * (gm.y * rsqrtf(vr.y + BN_EPS)) + bt.y;
    float y2 = (acc.z + bb.z - mn.z) * (gm.z * rsqrtf(vr.z + BN_EPS)) + bt.z;
    float y3 = (acc.w + bb.w - mn.w) * (gm.w * rsqrtf(vr.w + BN_EPS)) + bt.w;
    y0 = (y0 > 0.f) ? y0 : expm1f(y0);
    y1 = (y1 > 0.f) ? y1 : expm1f(y1);
    y2 = (y2 > 0.f) ? y2 : expm1f(y2);
    y3 = (y3 > 0.f) ? y3 : expm1f(y3);

    float h0 = __bfloat162float(__float2bfloat16(y0));
    float h1 = __bfloat162float(__float2bfloat16(y1));
    float h2 = __bfloat162float(__float2bfloat16(y2));
    float h3 = __bfloat162float(__float2bfloat16(y3));

    size_t o = (size_t)i * 64 + 2 * lane;   // bf162 index
    g_h1h2[o]     = __floats2bfloat162_rn(h0, h1);
    g_h1h2[o + 1] = __floats2bfloat162_rn(h2, h3);
    g_h1l2[o]     = __floats2bfloat162_rn(y0 - h0, y1 - h1);
    g_h1l2[o + 1] = __floats2bfloat162_rn(y2 - h2, y3 - h3);
}

// ---------------- aggregation 2 + final fusion mean --------------------------
__global__ __launch_bounds__(256) void k_agg2(const float* __restrict__ emb,
                       const float* __restrict__ b1,
                       float* __restrict__ out) {
    int lane = threadIdx.x & 31;
    int i = blockIdx.x * 8 + (threadIdx.x >> 5);

    float4 acc = agg_gather_w(g_g2, i, lane);

    float4 bb = *(const float4*)(b1 + 4 * lane);
    size_t o = (size_t)i * 128 + 4 * lane;
    float4 em = *(const float4*)(emb + o);

    size_t o2 = (size_t)i * 64 + 2 * lane;
    __nv_bfloat162 ha = g_h1h2[o2], hb = g_h1h2[o2 + 1];
    __nv_bfloat162 la = g_h1l2[o2], lb = g_h1l2[o2 + 1];
    float h1x = __bfloat162float(ha.x) + __bfloat162float(la.x);
    float h1y = __bfloat162float(ha.y) + __bfloat162float(la.y);
    float h1z = __bfloat162float(hb.x) + __bfloat162float(lb.x);
    float h1w = __bfloat162float(hb.y) + __bfloat162float(lb.y);

    float4 r;
    r.x = (em.x + h1x + acc.x + bb.x) * (1.0f / 3.0f);
    r.y = (em.y + h1y + acc.y + bb.y) * (1.0f / 3.0f);
    r.z = (em.z + h1z + acc.z + bb.z) * (1.0f / 3.0f);
    r.w = (em.w + h1w + acc.w + bb.w) * (1.0f / 3.0f);
    *(float4*)(out + o) = r;
}

// ---------------- launch: fork/join overlap + pipelined agg1/gemm2 -----------
extern "C" void kernel_launch(void* const* d_in, const int* in_sizes, int n_in,
                              void* d_out, int out_size) {
    const float* emb   = (const float*)d_in[0];
    const int*   ei    = (const int*)  d_in[1];
    const float* ew    = (const float*)d_in[2];
    const float* W0    = (const float*)d_in[3];
    const float* b0    = (const float*)d_in[4];
    const float* W1    = (const float*)d_in[5];
    const float* b1    = (const float*)d_in[6];
    const float* gamma = (const float*)d_in[7];
    const float* beta  = (const float*)d_in[8];
    const float* mean  = (const float*)d_in[9];
    const float* var   = (const float*)d_in[10];
    float* out = (float*)d_out;

    const int* row = ei;        // edge_index[0]
    const int* col = ei + EE;   // edge_index[1]

    const int NB_E = (EE + 255) / 256;
    const int NTILE = (NN + 127) / 128;      // 391
    const int T_A = NHALF / 128;             // 196 tiles (rows 0..25088)
    const int T_B = NTILE - T_A;             // 195 tiles
    const int BLK_A = NHALF / 8;             // 3136 agg1 blocks (nodes 0..25088)
    const int BLK_B = (NN - NHALF) / 8;      // 3114 blocks (24912 nodes)

    // one-time handles (no device memory; identical work every call)
    static cudaStream_t s_side = ([]() {
        cudaStream_t t;
        cudaStreamCreateWithFlags(&t, cudaStreamNonBlocking);
        return t;
    })();
    static cudaEvent_t s_fork = ([]() {
        cudaEvent_t e;
        cudaEventCreateWithFlags(&e, cudaEventDisableTiming);
        return e;
    })();
    static cudaEvent_t s_join = ([]() {
        cudaEvent_t e;
        cudaEventCreateWithFlags(&e, cudaEventDisableTiming);
        return e;
    })();
    static cudaEvent_t s_evA = ([]() {
        cudaEvent_t e;
        cudaEventCreateWithFlags(&e, cudaEventDisableTiming);
        return e;
    })();
    static cudaEvent_t s_evB = ([]() {
        cudaEvent_t e;
        cudaEventCreateWithFlags(&e, cudaEventDisableTiming);
        return e;
    })();
    static bool s_attr = ([]() {
        cudaFuncSetAttribute(k_gemm_mma,
                             cudaFuncAttributeMaxDynamicSharedMemorySize, SM_TOT);
        return true;
    })();
    (void)s_attr;

    // fork: side branch = W split + GEMM1 (independent of graph prep)
    cudaEventRecord(s_fork, 0);
    cudaStreamWaitEvent(s_side, s_fork, 0);
    k_split_w<<<32, 256, 0, s_side>>>(W0, W1);
    k_gemm_mma<<<NTILE, 256, SM_TOT, s_side>>>(emb, 0, 0);   // g_h2 = emb @ W0
    cudaEventRecord(s_join, s_side);

    // main branch: graph norm + CSC build
    k_deg    <<<NB_E, 256>>>(col, ew);
    k_bsum   <<<NSCAN_BLK, 256>>>();
    k_scan3  <<<NSCAN_BLK, 256>>>();
    k_scatter<<<NB_E, 256>>>(row, col, ew);

    // join, then pipelined second layer:
    //   agg1[0,NHALF) -> {side: gemm2 tiles [0,T_A)} || {main: agg1 rest + gemm2 rest}
    cudaStreamWaitEvent(0, s_join, 0);
    k_agg1<<<BLK_A, 256>>>(b0, gamma, beta, mean, var, 0);
    cudaEventRecord(s_evA, 0);
    cudaStreamWaitEvent(s_side, s_evA, 0);
    k_gemm_mma<<<T_A, 256, SM_TOT, s_side>>>(nullptr, 1, 0);
    cudaEventRecord(s_evB, s_side);
    k_agg1<<<BLK_B, 256>>>(b0, gamma, beta, mean, var, NHALF);
    k_gemm_mma<<<T_B, 256, SM_TOT>>>(nullptr, 1, T_A);
    cudaStreamWaitEvent(0, s_evB, 0);
    k_agg2<<<NN / 8, 256>>>(emb, b1, out);
}

// round 14
// speedup vs baseline: 1.0613x; 1.0031x over previous
#include <cuda_runtime.h>
#include <cuda_bf16.h>
#include <cuda_fp16.h>
#include <math.h>
#include <stdint.h>

#define NN 50000
#define EE 800000
#define DD 128
#define BN_EPS 1e-5f
#define NSCAN_BLK 196   // ceil(50000/256)

// ---------------- scratch (static device globals; no allocation) -------------
// Self-resetting protocol: g_degx and g_cnt start at 0 (BSS zero-init), are
// accumulated by k_deg, and are reset to 0 by their LAST reader each call.
__device__ float g_degx[NN];
__device__ float g_dis[NN];
__device__ int   g_cnt[NN];
__device__ int   g_off[NN];
__device__ int   g_cur[NN];
__device__ int   g_bsum[256];
__device__ int2  g_ed[EE];              // packed (src, weight-bits) per edge
__device__ __half2 g_h2[NN * 64];       // emb @ W0   (fp16, agg gather operand)
__device__ __half2 g_g2[NN * 64];       // h1 @ W1    (fp16, agg gather operand)
__device__ __nv_bfloat162 g_h1h2[NN * 64];  // h1 split hi (GEMM2 input)
__device__ __nv_bfloat162 g_h1l2[NN * 64];  // h1 split lo

// ---------------- small helpers ---------------------------------------------
__device__ __forceinline__ uint32_t smem_u32(const void* p) {
    uint32_t a;
    asm("{ .reg .u64 t; cvta.to.shared.u64 t, %1; cvt.u32.u64 %0, t; }"
        : "=r"(a) : "l"(p));
    return a;
}

__device__ __forceinline__ uint32_t pack_bf16x2(float lo, float hi) {
    __nv_bfloat162 t = __floats2bfloat162_rn(lo, hi);   // .x = lo half
    return *(uint32_t*)&t;
}

#define LDSM4(r0, r1, r2, r3, addr) \
    asm volatile("ldmatrix.sync.aligned.m8n8.x4.shared.b16 {%0,%1,%2,%3}, [%4];" \
                 : "=r"(r0), "=r"(r1), "=r"(r2), "=r"(r3) : "r"(addr))

#define LDSM4T(r0, r1, r2, r3, addr) \
    asm volatile("ldmatrix.sync.aligned.m8n8.x4.trans.shared.b16 {%0,%1,%2,%3}, [%4];" \
                 : "=r"(r0), "=r"(r1), "=r"(r2), "=r"(r3) : "r"(addr))

#define MMA16816(c, a0, a1, a2, a3, b0, b1) \
    asm volatile("mma.sync.aligned.m16n8k16.row.col.f32.bf16.bf16.f32 " \
                 "{%0,%1,%2,%3}, {%4,%5,%6,%7}, {%8,%9}, {%0,%1,%2,%3};" \
                 : "+f"((c)[0]), "+f"((c)[1]), "+f"((c)[2]), "+f"((c)[3]) \
                 : "r"(a0), "r"(a1), "r"(a2), "r"(a3), "r"(b0), "r"(b1))

// split a float4 into hi/lo bf16 pairs and store 8 bytes to each buffer
__device__ __forceinline__ void split_store(__nv_bfloat16* H, __nv_bfloat16* L,
                                            int off, float4 v) {
    float hx = __bfloat162float(__float2bfloat16(v.x));
    float hy = __bfloat162float(__float2bfloat16(v.y));
    float hz = __bfloat162float(__float2bfloat16(v.z));
    float hw = __bfloat162float(__float2bfloat16(v.w));
    uint2 hp = make_uint2(pack_bf16x2(hx, hy), pack_bf16x2(hz, hw));
    uint2 lp = make_uint2(pack_bf16x2(v.x - hx, v.y - hy),
                          pack_bf16x2(v.z - hz, v.w - hw));
    *(uint2*)(H + off) = hp;
    *(uint2*)(L + off) = lp;
}

// ---------------- norm + CSC build ------------------------------------------
__global__ void k_deg(const int* __restrict__ col, const float* __restrict__ w) {
    int e = blockIdx.x * blockDim.x + threadIdx.x;
    if (e < EE) {
        int c = col[e];
        atomicAdd(&g_degx[c], w[e]);
        atomicAdd(&g_cnt[c], 1);
    }
}

// per-block sum of counts (scan level 1) + fused deg^-1/2 + g_degx reset
__global__ void k_bsum() {
    int i = blockIdx.x * 256 + threadIdx.x;
    int v = (i < NN) ? g_cnt[i] : 0;
    if (i < NN) {
        g_dis[i] = rsqrtf(1.0f + g_degx[i]);   // +1.0 = self-loop weight
        g_degx[i] = 0.0f;                      // reset for next call
    }

#pragma unroll
    for (int o = 16; o > 0; o >>= 1) v += __shfl_down_sync(0xffffffffu, v, o);
    __shared__ int ws[8];
    int lane = threadIdx.x & 31, wid = threadIdx.x >> 5;
    if (lane == 0) ws[wid] = v;
    __syncthreads();
    if (threadIdx.x < 8) {
        int s = ws[threadIdx.x];
#pragma unroll
        for (int o = 4; o > 0; o >>= 1) s += __shfl_down_sync(0xffu, s, o);
        if (threadIdx.x == 0) g_bsum[blockIdx.x] = s;
    }
}

// scan level 2+3 fused: every block redundantly scans the 196 block sums in
// shared memory (cheap), then does its local scan; resets g_cnt.
__global__ void k_scan3() {
    __shared__ int bs[256];
    int t = threadIdx.x;
    bs[t] = (t < NSCAN_BLK) ? g_bsum[t] : 0;
    __syncthreads();
#pragma unroll
    for (int d = 1; d < 256; d <<= 1) {
        int u = (t >= d) ? bs[t - d] : 0;
        __syncthreads();
        bs[t] += u;
        __syncthreads();
    }
    int blk_base = (blockIdx.x == 0) ? 0 : bs[blockIdx.x - 1];

    int i = blockIdx.x * 256 + t;
    int v = (i < NN) ? g_cnt[i] : 0;
    int lane = t & 31, wid = t >> 5;

    int x = v;
#pragma unroll
    for (int o = 1; o < 32; o <<= 1) {
        int y = __shfl_up_sync(0xffffffffu, x, o);
        if (lane >= o) x += y;
    }
    __shared__ int wsum[8];
    if (lane == 31) wsum[wid] = x;
    __syncthreads();
    if (t < 8) {
        int s = wsum[t];
#pragma unroll
        for (int o = 1; o < 8; o <<= 1) {
            int y = __shfl_up_sync(0xffu, s, o);
            if (t >= o) s += y;
        }
        wsum[t] = s;
    }
    __syncthreads();
    int base = blk_base + ((wid > 0) ? wsum[wid - 1] : 0);
    int excl = base + x - v;
    if (i < NN) {
        g_off[i] = excl;
        g_cur[i] = excl;
        g_cnt[i] = 0;      // reset for next call (last reader)
    }
}

__global__ void k_scatter(const int* __restrict__ row, const int* __restrict__ col,
                          const float* __restrict__ w) {
    int e = blockIdx.x * blockDim.x + threadIdx.x;
    if (e < EE) {
        int r = row[e], c = col[e];
        int p = atomicAdd(&g_cur[c], 1);
        float wn = g_dis[r] * w[e] * g_dis[c];
        g_ed[p] = make_int2(r, __float_as_int(wn));   // one 8B scattered store
    }
}

// =============== tensor-core GEMM (bf16 3-term split, fused k-loop) ==========
// W is split from the raw fp32 input in-kernel (L2-resident, broadcast reads).
#define PITCH 136                      // bf16 elements per smem row (+8 pad)
#define MAT_BYTES (128 * PITCH * 2)    // 34816
#define SM_TOT (4 * MAT_BYTES)         // 139264

__global__ __launch_bounds__(256) void k_gemm_mma(const float* __restrict__ Af,
                                                  const float* __restrict__ W,
                                                  int sel) {
    extern __shared__ __align__(16) char sm[];
    __nv_bfloat16* Ah = (__nv_bfloat16*)(sm);
    __nv_bfloat16* Al = (__nv_bfloat16*)(sm + 1 * MAT_BYTES);
    __nv_bfloat16* Wh = (__nv_bfloat16*)(sm + 2 * MAT_BYTES);
    __nv_bfloat16* Wl = (__nv_bfloat16*)(sm + 3 * MAT_BYTES);

    __half2* C2 = (sel == 0) ? g_h2 : g_g2;

    int tid = threadIdx.x;
    int lane = tid & 31, wid = tid >> 5;
    int rowBase = blockIdx.x * 128;

    // ---- W tile: split raw fp32 -> hi/lo bf16 in SMEM (row k, cols n..n+3)
#pragma unroll
    for (int it = 0; it < 16; it++) {
        int idx = tid + it * 256;            // 0..4095 float4s
        int k = idx >> 5, n = (idx & 31) * 4;
        float4 v = *(const float4*)(W + k * 128 + n);
        split_store(Wh, Wl, k * PITCH + n, v);
    }

    if (sel == 0) {
#pragma unroll
        for (int it = 0; it < 16; it++) {
            int idx = tid + it * 256;        // 0..4095 float4s
            int r = idx >> 5, c = (idx & 31) * 4;
            int gr = rowBase + r;
            float4 v = (gr < NN) ? *(const float4*)(Af + (size_t)gr * 128 + c)
                                 : make_float4(0.f, 0.f, 0.f, 0.f);
            split_store(Ah, Al, r * PITCH + c, v);
        }
    } else {
        const uint4 zz = make_uint4(0, 0, 0, 0);
        const uint4* H4 = (const uint4*)g_h1h2;
        const uint4* L4 = (const uint4*)g_h1l2;
#pragma unroll
        for (int it = 0; it < 8; it++) {
            int idx = tid + it * 256;        // 0..2047 uint4s
            int r = idx >> 4, q = idx & 15;  // q = 16-byte chunk (8 bf16)
            int gr = rowBase + r;
            uint4 vh = zz, vl = zz;
            if (gr < NN) {
                vh = H4[(size_t)gr * 16 + q];
                vl = L4[(size_t)gr * 16 + q];
            }
            *(uint4*)(Ah + r * PITCH + q * 8) = vh;
            *(uint4*)(Al + r * PITCH + q * 8) = vl;
        }
    }
    __syncthreads();

    int m0 = (wid & 3) * 32;
    int n0 = (wid >> 2) * 64;

    float acc[2][8][4];
#pragma unroll
    for (int mt = 0; mt < 2; mt++)
#pragma unroll
        for (int j = 0; j < 8; j++)
#pragma unroll
            for (int q = 0; q < 4; q++) acc[mt][j][q] = 0.f;

    uint32_t AhB = smem_u32(Ah), AlB = smem_u32(Al);
    uint32_t WhB = smem_u32(Wh), WlB = smem_u32(Wl);
    int a_r = lane & 15, a_c8 = (lane >> 4) << 3;
    int b_k = lane & 15, b_n8 = (lane >> 4) << 3;

#pragma unroll
    for (int ks = 0; ks < 8; ks++) {
        int k0 = ks * 16;
        uint32_t ah[2][4], al[2][4];
#pragma unroll
        for (int mt = 0; mt < 2; mt++) {
            uint32_t aoff = (uint32_t)((m0 + mt * 16 + a_r) * PITCH + k0 + a_c8) * 2;
            LDSM4(ah[mt][0], ah[mt][1], ah[mt][2], ah[mt][3], AhB + aoff);
            LDSM4(al[mt][0], al[mt][1], al[mt][2], al[mt][3], AlB + aoff);
        }
#pragma unroll
        for (int nt = 0; nt < 4; nt++) {
            uint32_t boff = (uint32_t)((k0 + b_k) * PITCH + n0 + nt * 16 + b_n8) * 2;
            uint32_t bh0, bh1, bh2, bh3, bl0, bl1, bl2, bl3;
            LDSM4T(bh0, bh1, bh2, bh3, WhB + boff);
            LDSM4T(bl0, bl1, bl2, bl3, WlB + boff);
#pragma unroll
            for (int mt = 0; mt < 2; mt++) {
                MMA16816(acc[mt][2 * nt],     ah[mt][0], ah[mt][1], ah[mt][2], ah[mt][3], bh0, bh1);
                MMA16816(acc[mt][2 * nt + 1], ah[mt][0], ah[mt][1], ah[mt][2], ah[mt][3], bh2, bh3);
                MMA16816(acc[mt][2 * nt],     ah[mt][0], ah[mt][1], ah[mt][2], ah[mt][3], bl0, bl1);
                MMA16816(acc[mt][2 * nt + 1], ah[mt][0], ah[mt][1], ah[mt][2], ah[mt][3], bl2, bl3);
                MMA16816(acc[mt][2 * nt],     al[mt][0], al[mt][1], al[mt][2], al[mt][3], bh0, bh1);
                MMA16816(acc[mt][2 * nt + 1], al[mt][0], al[mt][1], al[mt][2], al[mt][3], bh2, bh3);
            }
        }
    }

    // ---- epilogue: native __half2 stores (cc even -> n0+j*8+cc even)
    int rr = lane >> 2, cc = (lane & 3) * 2;
#pragma unroll
    for (int mt = 0; mt < 2; mt++) {
        int r0 = rowBase + m0 + mt * 16 + rr;
        bool v0 = r0 < NN, v1 = (r0 + 8) < NN;
#pragma unroll
        for (int j = 0; j < 8; j++) {
            int n2 = (n0 + j * 8 + cc) >> 1;
            if (v0) C2[(size_t)r0 * 64 + n2]
                        = __floats2half2_rn(acc[mt][j][0], acc[mt][j][1]);
            if (v1) C2[(size_t)(r0 + 8) * 64 + n2]
                        = __floats2half2_rn(acc[mt][j][2], acc[mt][j][3]);
        }
    }
}

// ======= aggregation core: ONE WARP per node, half2 lanes, unroll 8 ==========
// lane owns features [4*lane, 4*lane+4) = half2 elements {2*lane, 2*lane+1}.
__device__ __forceinline__ float4 agg_gather_w(const __half2* __restrict__ H2,
                                               int i, int lane) {
    float di = g_dis[i];
    float sw = di * di;
    size_t sb = (size_t)i * 64 + 2 * lane;
    float2 sa = __half22float2(H2[sb]);
    float2 sc = __half22float2(H2[sb + 1]);
    float4 a0 = make_float4(sw * sa.x, sw * sa.y, sw * sc.x, sw * sc.y);
    float4 a1 = make_float4(0.f, 0.f, 0.f, 0.f);
    float4 a2 = a1, a3 = a1;

    int s = g_off[i];
    int n = ((i + 1 < NN) ? g_off[i + 1] : EE) - s;
    const int2 zz = make_int2(0, 0);

    for (int p = 0; p < n; p += 8) {
        bool u1 = p + 1 < n, u2 = p + 2 < n, u3 = p + 3 < n;
        bool u4 = p + 4 < n, u5 = p + 5 < n, u6 = p + 6 < n, u7 = p + 7 < n;
        int2 e0 = g_ed[s + p];
        int2 e1 = u1 ? g_ed[s + p + 1] : zz;
        int2 e2 = u2 ? g_ed[s + p + 2] : zz;
        int2 e3 = u3 ? g_ed[s + p + 3] : zz;
        int2 e4 = u4 ? g_ed[s + p + 4] : zz;
        int2 e5 = u5 ? g_ed[s + p + 5] : zz;
        int2 e6 = u6 ? g_ed[s + p + 6] : zz;
        int2 e7 = u7 ? g_ed[s + p + 7] : zz;

        float w0 = __int_as_float(e0.y), w1 = __int_as_float(e1.y);
        float w2 = __int_as_float(e2.y), w3 = __int_as_float(e3.y);
        float w4 = __int_as_float(e4.y), w5 = __int_as_float(e5.y);
        float w6 = __int_as_float(e6.y), w7 = __int_as_float(e7.y);

        size_t b0 = (size_t)e0.x * 64 + 2 * lane;
        size_t b1 = (size_t)e1.x * 64 + 2 * lane;
        size_t b2 = (size_t)e2.x * 64 + 2 * lane;
        size_t b3 = (size_t)e3.x * 64 + 2 * lane;
        size_t b4 = (size_t)e4.x * 64 + 2 * lane;
        size_t b5 = (size_t)e5.x * 64 + 2 * lane;
        size_t b6 = (size_t)e6.x * 64 + 2 * lane;
        size_t b7 = (size_t)e7.x * 64 + 2 * lane;
        float2 h0a = __half22float2(H2[b0]), h0b = __half22float2(H2[b0 + 1]);
        float2 h1a = __half22float2(H2[b1]), h1b = __half22float2(H2[b1 + 1]);
        float2 h2a = __half22float2(H2[b2]), h2b = __half22float2(H2[b2 + 1]);
        float2 h3a = __half22float2(H2[b3]), h3b = __half22float2(H2[b3 + 1]);
        float2 h4a = __half22float2(H2[b4]), h4b = __half22float2(H2[b4 + 1]);
        float2 h5a = __half22float2(H2[b5]), h5b = __half22float2(H2[b5 + 1]);
        float2 h6a = __half22float2(H2[b6]), h6b = __half22float2(H2[b6 + 1]);
        float2 h7a = __half22float2(H2[b7]), h7b = __half22float2(H2[b7 + 1]);

        a0.x += w0 * h0a.x; a0.y += w0 * h0a.y; a0.z += w0 * h0b.x; a0.w += w0 * h0b.y;
        a1.x += w1 * h1a.x; a1.y += w1 * h1a.y; a1.z += w1 * h1b.x; a1.w += w1 * h1b.y;
        a2.x += w2 * h2a.x; a2.y += w2 * h2a.y; a2.z += w2 * h2b.x; a2.w += w2 * h2b.y;
        a3.x += w3 * h3a.x; a3.y += w3 * h3a.y; a3.z += w3 * h3b.x; a3.w += w3 * h3b.y;
        a0.x += w4 * h4a.x; a0.y += w4 * h4a.y; a0.z += w4 * h4b.x; a0.w += w4 * h4b.y;
        a1.x += w5 * h5a.x; a1.y += w5 * h5a.y; a1.z += w5 * h5b.x; a1.w += w5 * h5b.y;
        a2.x += w6 * h6a.x; a2.y += w6 * h6a.y; a2.z += w6 * h6b.x; a2.w += w6 * h6b.y;
        a3.x += w7 * h7a.x; a3.y += w7 * h7a.y; a3.z += w7 * h7b.x; a3.w += w7 * h7b.y;
    }
    return make_float4((a0.x + a1.x) + (a2.x + a3.x),
                       (a0.y + a1.y) + (a2.y + a3.y),
                       (a0.z + a1.z) + (a2.z + a3.z),
                       (a0.w + a1.w) + (a2.w + a3.w));
}

// ---------------- aggregation 1: conv1 + bias + BN + ELU -> bf16 split -------
__global__ __launch_bounds__(256) void k_agg1(const float* __restrict__ b0,
                       const float* __restrict__ gamma,
                       const float* __restrict__ beta,
                       const float* __restrict__ mean,
                       const float* __restrict__ var) {
    int lane = threadIdx.x & 31;
    int i = blockIdx.x * 8 + (threadIdx.x >> 5);   // 6250 * 8 = 50000 exact

    float4 acc = agg_gather_w(g_h2, i, lane);

    float4 bb = *(const float4*)(b0    + 4 * lane);
    float4 gm = *(const float4*)(gamma + 4 * lane);
    float4 bt = *(const float4*)(beta  + 4 * lane);
    float4 mn = *(const float4*)(mean  + 4 * lane);
    float4 vr = *(const float4*)(var   + 4 * lane);

    float y0 = (acc.x + bb.x - mn.x) * (gm.x * rsqrtf(vr.x + BN_EPS)) + bt.x;
    float y1 = (acc.y + bb.y - mn.y) * (gm.y * rsqrtf(vr.y + BN_EPS)) + bt.y;
    float y2 = (acc.z + bb.z - mn.z) * (gm.z * rsqrtf(vr.z + BN_EPS)) + bt.z;
    float y3 = (acc.w + bb.w - mn.w) * (gm.w * rsqrtf(vr.w + BN_EPS)) + bt.w;
    y0 = (y0 > 0.f) ? y0 : expm1f(y0);
    y1 = (y1 > 0.f) ? y1 : expm1f(y1);
    y2 = (y2 > 0.f) ? y2 : expm1f(y2);
    y3 = (y3 > 0.f) ? y3 : expm1f(y3);

    float h0 = __bfloat162float(__float2bfloat16(y0));
    float h1 = __bfloat162float(__float2bfloat16(y1));
    float h2 = __bfloat162float(__float2bfloat16(y2));
    float h3 = __bfloat162float(__float2bfloat16(y3));

    size_t o = (size_t)i * 64 + 2 * lane;   // bf162 index
    g_h1h2[o]     = __floats2bfloat162_rn(h0, h1);
    g_h1h2[o + 1] = __floats2bfloat162_rn(h2, h3);
    g_h1l2[o]     = __floats2bfloat162_rn(y0 - h0, y1 - h1);
    g_h1l2[o + 1] = __floats2bfloat162_rn(y2 - h2, y3 - h3);
}

// ---------------- aggregation 2 + final fusion mean --------------------------
__global__ __launch_bounds__(256) void k_agg2(const float* __restrict__ emb,
                       const float* __restrict__ b1,
                       float* __restrict__ out) {
    int lane = threadIdx.x & 31;
    int i = blockIdx.x * 8 + (threadIdx.x >> 5);

    float4 acc = agg_gather_w(g_g2, i, lane);

    float4 bb = *(const float4*)(b1 + 4 * lane);
    size_t o = (size_t)i * 128 + 4 * lane;
    float4 em = *(const float4*)(emb + o);

    size_t o2 = (size_t)i * 64 + 2 * lane;
    __nv_bfloat162 ha = g_h1h2[o2], hb = g_h1h2[o2 + 1];
    __nv_bfloat162 la = g_h1l2[o2], lb = g_h1l2[o2 + 1];
    float h1x = __bfloat162float(ha.x) + __bfloat162float(la.x);
    float h1y = __bfloat162float(ha.y) + __bfloat162float(la.y);
    float h1z = __bfloat162float(hb.x) + __bfloat162float(lb.x);
    float h1w = __bfloat162float(hb.y) + __bfloat162float(lb.y);

    float4 r;
    r.x = (em.x + h1x + acc.x + bb.x) * (1.0f / 3.0f);
    r.y = (em.y + h1y + acc.y + bb.y) * (1.0f / 3.0f);
    r.z = (em.z + h1z + acc.z + bb.z) * (1.0f / 3.0f);
    r.w = (em.w + h1w + acc.w + bb.w) * (1.0f / 3.0f);
    *(float4*)(out + o) = r;
}

// ---------------- launch: fork/join so GEMM1 overlaps graph prep -------------
extern "C" void kernel_launch(void* const* d_in, const int* in_sizes, int n_in,
                              void* d_out, int out_size) {
    const float* emb   = (const float*)d_in[0];
    const int*   ei    = (const int*)  d_in[1];
    const float* ew    = (const float*)d_in[2];
    const float* W0    = (const float*)d_in[3];
    const float* b0    = (const float*)d_in[4];
    const float* W1    = (const float*)d_in[5];
    const float* b1    = (const float*)d_in[6];
    const float* gamma = (const float*)d_in[7];
    const float* beta  = (const float*)d_in[8];
    const float* mean  = (const float*)d_in[9];
    const float* var   = (const float*)d_in[10];
    float* out = (float*)d_out;

    const int* row = ei;        // edge_index[0]
    const int* col = ei + EE;   // edge_index[1]

    const int NB_E = (EE + 255) / 256;
    const int NTILE = (NN + 127) / 128;   // 391

    // one-time handles (no device memory; identical work every call)
    static cudaStream_t s_side = ([]() {
        cudaStream_t t;
        cudaStreamCreateWithFlags(&t, cudaStreamNonBlocking);
        return t;
    })();
    static cudaEvent_t s_fork = ([]() {
        cudaEvent_t e;
        cudaEventCreateWithFlags(&e, cudaEventDisableTiming);
        return e;
    })();
    static cudaEvent_t s_join = ([]() {
        cudaEvent_t e;
        cudaEventCreateWithFlags(&e, cudaEventDisableTiming);
        return e;
    })();
    static bool s_attr = ([]() {
        cudaFuncSetAttribute(k_gemm_mma,
                             cudaFuncAttributeMaxDynamicSharedMemorySize, SM_TOT);
        return true;
    })();
    (void)s_attr;

    // fork: side branch = GEMM1 (independent of graph prep; splits W0 itself)
    cudaEventRecord(s_fork, 0);
    cudaStreamWaitEvent(s_side, s_fork, 0);
    k_gemm_mma<<<NTILE, 256, SM_TOT, s_side>>>(emb, W0, 0);   // g_h2 = emb @ W0
    cudaEventRecord(s_join, s_side);

    // main branch: graph norm + CSC build
    k_deg    <<<NB_E, 256>>>(col, ew);
    k_bsum   <<<NSCAN_BLK, 256>>>();
    k_scan3  <<<NSCAN_BLK, 256>>>();
    k_scatter<<<NB_E, 256>>>(row, col, ew);

    // join, then the dependent tail
    cudaStreamWaitEvent(0, s_join, 0);
    k_agg1<<<NN / 8, 256>>>(b0, gamma, beta, mean, var);
    k_gemm_mma<<<NTILE, 256, SM_TOT>>>(nullptr, W1, 1);       // g_g2 = h1 @ W1
    k_agg2<<<NN / 8, 256>>>(emb, b1, out);
}

// round 15
// speedup vs baseline: 1.1009x; 1.0373x over previous
#include <cuda_runtime.h>
#include <cuda_bf16.h>
#include <cuda_fp16.h>
#include <math.h>
#include <stdint.h>

#define NN 50000
#define EE 800000
#define DD 128
#define BN_EPS 1e-5f
#define NSCAN_BLK 196   // ceil(50000/256)

// ---------------- scratch (static device globals; no allocation) -------------
// Self-resetting protocol: g_pk and g_cnt start at 0 (BSS zero-init), are
// accumulated by k_deg, and are reset to 0 by their LAST reader each call.
__device__ unsigned long long g_pk[NN]; // packed: count<<40 | fix24(sum w)
__device__ float g_dis[NN];
__device__ int   g_cnt[NN];
__device__ int   g_off[NN];
__device__ int   g_cur[NN];
__device__ int   g_bsum[256];
__device__ int2  g_ed[EE];              // packed (src, weight-bits) per edge
__device__ __half2 g_h2[NN * 64];       // emb @ W0   (fp16, agg gather operand)
__device__ __half2 g_g2[NN * 64];       // h1 @ W1    (fp16, agg gather operand)
__device__ __nv_bfloat162 g_h1h2[NN * 64];  // h1 split hi (GEMM2 input)
__device__ __nv_bfloat162 g_h1l2[NN * 64];  // h1 split lo

// ---------------- small helpers ---------------------------------------------
__device__ __forceinline__ uint32_t smem_u32(const void* p) {
    uint32_t a;
    asm("{ .reg .u64 t; cvta.to.shared.u64 t, %1; cvt.u32.u64 %0, t; }"
        : "=r"(a) : "l"(p));
    return a;
}

__device__ __forceinline__ uint32_t pack_bf16x2(float lo, float hi) {
    __nv_bfloat162 t = __floats2bfloat162_rn(lo, hi);   // .x = lo half
    return *(uint32_t*)&t;
}

#define LDSM4(r0, r1, r2, r3, addr) \
    asm volatile("ldmatrix.sync.aligned.m8n8.x4.shared.b16 {%0,%1,%2,%3}, [%4];" \
                 : "=r"(r0), "=r"(r1), "=r"(r2), "=r"(r3) : "r"(addr))

#define LDSM4T(r0, r1, r2, r3, addr) \
    asm volatile("ldmatrix.sync.aligned.m8n8.x4.trans.shared.b16 {%0,%1,%2,%3}, [%4];" \
                 : "=r"(r0), "=r"(r1), "=r"(r2), "=r"(r3) : "r"(addr))

#define MMA16816(c, a0, a1, a2, a3, b0, b1) \
    asm volatile("mma.sync.aligned.m16n8k16.row.col.f32.bf16.bf16.f32 " \
                 "{%0,%1,%2,%3}, {%4,%5,%6,%7}, {%8,%9}, {%0,%1,%2,%3};" \
                 : "+f"((c)[0]), "+f"((c)[1]), "+f"((c)[2]), "+f"((c)[3]) \
                 : "r"(a0), "r"(a1), "r"(a2), "r"(a3), "r"(b0), "r"(b1))

// split a float4 into hi/lo bf16 pairs and store 8 bytes to each buffer
__device__ __forceinline__ void split_store(__nv_bfloat16* H, __nv_bfloat16* L,
                                            int off, float4 v) {
    float hx = __bfloat162float(__float2bfloat16(v.x));
    float hy = __bfloat162float(__float2bfloat16(v.y));
    float hz = __bfloat162float(__float2bfloat16(v.z));
    float hw = __bfloat162float(__float2bfloat16(v.w));
    uint2 hp = make_uint2(pack_bf16x2(hx, hy), pack_bf16x2(hz, hw));
    uint2 lp = make_uint2(pack_bf16x2(v.x - hx, v.y - hy),
                          pack_bf16x2(v.z - hz, v.w - hw));
    *(uint2*)(H + off) = hp;
    *(uint2*)(L + off) = lp;
}

// ---------------- norm + CSC build ------------------------------------------
// One packed 64-bit atomic per edge: count in bits [40..], weight sum as
// 24-bit fixed point in the low bits (w in [0,1), deg <= ~50 -> sum < 2^30).
__global__ void k_deg(const int* __restrict__ col, const float* __restrict__ w) {
    int e = blockIdx.x * blockDim.x + threadIdx.x;
    if (e < EE) {
        int c = col[e];
        unsigned long long inc = (1ULL << 40)
            + (unsigned long long)(w[e] * 16777216.0f);   // 2^24 fixed point
        atomicAdd(&g_pk[c], inc);
    }
}

// per-block sum of counts (scan level 1) + fused deg^-1/2 + g_pk reset
__global__ void k_bsum() {
    int i = blockIdx.x * 256 + threadIdx.x;
    int v = 0;
    if (i < NN) {
        unsigned long long pk = g_pk[i];
        v = (int)(pk >> 40);
        float deg = (float)(pk & ((1ULL << 40) - 1)) * (1.0f / 16777216.0f);
        g_dis[i] = rsqrtf(1.0f + deg);         // +1.0 = self-loop weight
        g_cnt[i] = v;
        g_pk[i] = 0ULL;                        // reset for next call
    }

#pragma unroll
    for (int o = 16; o > 0; o >>= 1) v += __shfl_down_sync(0xffffffffu, v, o);
    __shared__ int ws[8];
    int lane = threadIdx.x & 31, wid = threadIdx.x >> 5;
    if (lane == 0) ws[wid] = v;
    __syncthreads();
    if (threadIdx.x < 8) {
        int s = ws[threadIdx.x];
#pragma unroll
        for (int o = 4; o > 0; o >>= 1) s += __shfl_down_sync(0xffu, s, o);
        if (threadIdx.x == 0) g_bsum[blockIdx.x] = s;
    }
}

// scan level 2+3 fused: every block redundantly scans the 196 block sums in
// shared memory (cheap), then does its local scan; resets g_cnt.
__global__ void k_scan3() {
    __shared__ int bs[256];
    int t = threadIdx.x;
    bs[t] = (t < NSCAN_BLK) ? g_bsum[t] : 0;
    __syncthreads();
#pragma unroll
    for (int d = 1; d < 256; d <<= 1) {
        int u = (t >= d) ? bs[t - d] : 0;
        __syncthreads();
        bs[t] += u;
        __syncthreads();
    }
    int blk_base = (blockIdx.x == 0) ? 0 : bs[blockIdx.x - 1];

    int i = blockIdx.x * 256 + t;
    int v = (i < NN) ? g_cnt[i] : 0;
    int lane = t & 31, wid = t >> 5;

    int x = v;
#pragma unroll
    for (int o = 1; o < 32; o <<= 1) {
        int y = __shfl_up_sync(0xffffffffu, x, o);
        if (lane >= o) x += y;
    }
    __shared__ int wsum[8];
    if (lane == 31) wsum[wid] = x;
    __syncthreads();
    if (t < 8) {
        int s = wsum[t];
#pragma unroll
        for (int o = 1; o < 8; o <<= 1) {
            int y = __shfl_up_sync(0xffu, s, o);
            if (t >= o) s += y;
        }
        wsum[t] = s;
    }
    __syncthreads();
    int base = blk_base + ((wid > 0) ? wsum[wid - 1] : 0);
    int excl = base + x - v;
    if (i < NN) {
        g_off[i] = excl;
        g_cur[i] = excl;
        g_cnt[i] = 0;      // reset for next call (last reader)
    }
}

__global__ void k_scatter(const int* __restrict__ row, const int* __restrict__ col,
                          const float* __restrict__ w) {
    int e = blockIdx.x * blockDim.x + threadIdx.x;
    if (e < EE) {
        int r = row[e], c = col[e];
        int p = atomicAdd(&g_cur[c], 1);
        float wn = g_dis[r] * w[e] * g_dis[c];
        g_ed[p] = make_int2(r, __float_as_int(wn));   // one 8B scattered store
    }
}

// =============== tensor-core GEMM (bf16 3-term split, fused k-loop) ==========
// W is split from the raw fp32 input in-kernel (L2-resident, broadcast reads).
#define PITCH 136                      // bf16 elements per smem row (+8 pad)
#define MAT_BYTES (128 * PITCH * 2)    // 34816
#define SM_TOT (4 * MAT_BYTES)         // 139264

__global__ __launch_bounds__(256) void k_gemm_mma(const float* __restrict__ Af,
                                                  const float* __restrict__ W,
                                                  int sel) {
    extern __shared__ __align__(16) char sm[];
    __nv_bfloat16* Ah = (__nv_bfloat16*)(sm);
    __nv_bfloat16* Al = (__nv_bfloat16*)(sm + 1 * MAT_BYTES);
    __nv_bfloat16* Wh = (__nv_bfloat16*)(sm + 2 * MAT_BYTES);
    __nv_bfloat16* Wl = (__nv_bfloat16*)(sm + 3 * MAT_BYTES);

    __half2* C2 = (sel == 0) ? g_h2 : g_g2;

    int tid = threadIdx.x;
    int lane = tid & 31, wid = tid >> 5;
    int rowBase = blockIdx.x * 128;

    // ---- W tile: split raw fp32 -> hi/lo bf16 in SMEM (row k, cols n..n+3)
#pragma unroll
    for (int it = 0; it < 16; it++) {
        int idx = tid + it * 256;            // 0..4095 float4s
        int k = idx >> 5, n = (idx & 31) * 4;
        float4 v = *(const float4*)(W + k * 128 + n);
        split_store(Wh, Wl, k * PITCH + n, v);
    }

    if (sel == 0) {
#pragma unroll
        for (int it = 0; it < 16; it++) {
            int idx = tid + it * 256;        // 0..4095 float4s
            int r = idx >> 5, c = (idx & 31) * 4;
            int gr = rowBase + r;
            float4 v = (gr < NN) ? *(const float4*)(Af + (size_t)gr * 128 + c)
                                 : make_float4(0.f, 0.f, 0.f, 0.f);
            split_store(Ah, Al, r * PITCH + c, v);
        }
    } else {
        const uint4 zz = make_uint4(0, 0, 0, 0);
        const uint4* H4 = (const uint4*)g_h1h2;
        const uint4* L4 = (const uint4*)g_h1l2;
#pragma unroll
        for (int it = 0; it < 8; it++) {
            int idx = tid + it * 256;        // 0..2047 uint4s
            int r = idx >> 4, q = idx & 15;  // q = 16-byte chunk (8 bf16)
            int gr = rowBase + r;
            uint4 vh = zz, vl = zz;
            if (gr < NN) {
                vh = H4[(size_t)gr * 16 + q];
                vl = L4[(size_t)gr * 16 + q];
            }
            *(uint4*)(Ah + r * PITCH + q * 8) = vh;
            *(uint4*)(Al + r * PITCH + q * 8) = vl;
        }
    }
    __syncthreads();

    int m0 = (wid & 3) * 32;
    int n0 = (wid >> 2) * 64;

    float acc[2][8][4];
#pragma unroll
    for (int mt = 0; mt < 2; mt++)
#pragma unroll
        for (int j = 0; j < 8; j++)
#pragma unroll
            for (int q = 0; q < 4; q++) acc[mt][j][q] = 0.f;

    uint32_t AhB = smem_u32(Ah), AlB = smem_u32(Al);
    uint32_t WhB = smem_u32(Wh), WlB = smem_u32(Wl);
    int a_r = lane & 15, a_c8 = (lane >> 4) << 3;
    int b_k = lane & 15, b_n8 = (lane >> 4) << 3;

#pragma unroll
    for (int ks = 0; ks < 8; ks++) {
        int k0 = ks * 16;
        uint32_t ah[2][4], al[2][4];
#pragma unroll
        for (int mt = 0; mt < 2; mt++) {
            uint32_t aoff = (uint32_t)((m0 + mt * 16 + a_r) * PITCH + k0 + a_c8) * 2;
            LDSM4(ah[mt][0], ah[mt][1], ah[mt][2], ah[mt][3], AhB + aoff);
            LDSM4(al[mt][0], al[mt][1], al[mt][2], al[mt][3], AlB + aoff);
        }
#pragma unroll
        for (int nt = 0; nt < 4; nt++) {
            uint32_t boff = (uint32_t)((k0 + b_k) * PITCH + n0 + nt * 16 + b_n8) * 2;
            uint32_t bh0, bh1, bh2, bh3, bl0, bl1, bl2, bl3;
            LDSM4T(bh0, bh1, bh2, bh3, WhB + boff);
            LDSM4T(bl0, bl1, bl2, bl3, WlB + boff);
#pragma unroll
            for (int mt = 0; mt < 2; mt++) {
                MMA16816(acc[mt][2 * nt],     ah[mt][0], ah[mt][1], ah[mt][2], ah[mt][3], bh0, bh1);
                MMA16816(acc[mt][2 * nt + 1], ah[mt][0], ah[mt][1], ah[mt][2], ah[mt][3], bh2, bh3);
                MMA16816(acc[mt][2 * nt],     ah[mt][0], ah[mt][1], ah[mt][2], ah[mt][3], bl0, bl1);
                MMA16816(acc[mt][2 * nt + 1], ah[mt][0], ah[mt][1], ah[mt][2], ah[mt][3], bl2, bl3);
                MMA16816(acc[mt][2 * nt],     al[mt][0], al[mt][1], al[mt][2], al[mt][3], bh0, bh1);
                MMA16816(acc[mt][2 * nt + 1], al[mt][0], al[mt][1], al[mt][2], al[mt][3], bh2, bh3);
            }
        }
    }

    // ---- epilogue: native __half2 stores (cc even -> n0+j*8+cc even)
    int rr = lane >> 2, cc = (lane & 3) * 2;
#pragma unroll
    for (int mt = 0; mt < 2; mt++) {
        int r0 = rowBase + m0 + mt * 16 + rr;
        bool v0 = r0 < NN, v1 = (r0 + 8) < NN;
#pragma unroll
        for (int j = 0; j < 8; j++) {
            int n2 = (n0 + j * 8 + cc) >> 1;
            if (v0) C2[(size_t)r0 * 64 + n2]
                        = __floats2half2_rn(acc[mt][j][0], acc[mt][j][1]);
            if (v1) C2[(size_t)(r0 + 8) * 64 + n2]
                        = __floats2half2_rn(acc[mt][j][2], acc[mt][j][3]);
        }
    }
}

// ======= aggregation core: ONE WARP per node, half2 lanes, unroll 8 ==========
// lane owns features [4*lane, 4*lane+4) = half2 elements {2*lane, 2*lane+1}.
__device__ __forceinline__ float4 agg_gather_w(const __half2* __restrict__ H2,
                                               int i, int lane) {
    float di = g_dis[i];
    float sw = di * di;
    size_t sb = (size_t)i * 64 + 2 * lane;
    float2 sa = __half22float2(H2[sb]);
    float2 sc = __half22float2(H2[sb + 1]);
    float4 a0 = make_float4(sw * sa.x, sw * sa.y, sw * sc.x, sw * sc.y);
    float4 a1 = make_float4(0.f, 0.f, 0.f, 0.f);
    float4 a2 = a1, a3 = a1;

    int s = g_off[i];
    int n = ((i + 1 < NN) ? g_off[i + 1] : EE) - s;
    const int2 zz = make_int2(0, 0);

    for (int p = 0; p < n; p += 8) {
        bool u1 = p + 1 < n, u2 = p + 2 < n, u3 = p + 3 < n;
        bool u4 = p + 4 < n, u5 = p + 5 < n, u6 = p + 6 < n, u7 = p + 7 < n;
        int2 e0 = g_ed[s + p];
        int2 e1 = u1 ? g_ed[s + p + 1] : zz;
        int2 e2 = u2 ? g_ed[s + p + 2] : zz;
        int2 e3 = u3 ? g_ed[s + p + 3] : zz;
        int2 e4 = u4 ? g_ed[s + p + 4] : zz;
        int2 e5 = u5 ? g_ed[s + p + 5] : zz;
        int2 e6 = u6 ? g_ed[s + p + 6] : zz;
        int2 e7 = u7 ? g_ed[s + p + 7] : zz;

        float w0 = __int_as_float(e0.y), w1 = __int_as_float(e1.y);
        float w2 = __int_as_float(e2.y), w3 = __int_as_float(e3.y);
        float w4 = __int_as_float(e4.y), w5 = __int_as_float(e5.y);
        float w6 = __int_as_float(e6.y), w7 = __int_as_float(e7.y);

        size_t b0 = (size_t)e0.x * 64 + 2 * lane;
        size_t b1 = (size_t)e1.x * 64 + 2 * lane;
        size_t b2 = (size_t)e2.x * 64 + 2 * lane;
        size_t b3 = (size_t)e3.x * 64 + 2 * lane;
        size_t b4 = (size_t)e4.x * 64 + 2 * lane;
        size_t b5 = (size_t)e5.x * 64 + 2 * lane;
        size_t b6 = (size_t)e6.x * 64 + 2 * lane;
        size_t b7 = (size_t)e7.x * 64 + 2 * lane;
        float2 h0a = __half22float2(H2[b0]), h0b = __half22float2(H2[b0 + 1]);
        float2 h1a = __half22float2(H2[b1]), h1b = __half22float2(H2[b1 + 1]);
        float2 h2a = __half22float2(H2[b2]), h2b = __half22float2(H2[b2 + 1]);
        float2 h3a = __half22float2(H2[b3]), h3b = __half22float2(H2[b3 + 1]);
        float2 h4a = __half22float2(H2[b4]), h4b = __half22float2(H2[b4 + 1]);
        float2 h5a = __half22float2(H2[b5]), h5b = __half22float2(H2[b5 + 1]);
        float2 h6a = __half22float2(H2[b6]), h6b = __half22float2(H2[b6 + 1]);
        float2 h7a = __half22float2(H2[b7]), h7b = __half22float2(H2[b7 + 1]);

        a0.x += w0 * h0a.x; a0.y += w0 * h0a.y; a0.z += w0 * h0b.x; a0.w += w0 * h0b.y;
        a1.x += w1 * h1a.x; a1.y += w1 * h1a.y; a1.z += w1 * h1b.x; a1.w += w1 * h1b.y;
        a2.x += w2 * h2a.x; a2.y += w2 * h2a.y; a2.z += w2 * h2b.x; a2.w += w2 * h2b.y;
        a3.x += w3 * h3a.x; a3.y += w3 * h3a.y; a3.z += w3 * h3b.x; a3.w += w3 * h3b.y;
        a0.x += w4 * h4a.x; a0.y += w4 * h4a.y; a0.z += w4 * h4b.x; a0.w += w4 * h4b.y;
        a1.x += w5 * h5a.x; a1.y += w5 * h5a.y; a1.z += w5 * h5b.x; a1.w += w5 * h5b.y;
        a2.x += w6 * h6a.x; a2.y += w6 * h6a.y; a2.z += w6 * h6b.x; a2.w += w6 * h6b.y;
        a3.x += w7 * h7a.x; a3.y += w7 * h7a.y; a3.z += w7 * h7b.x; a3.w += w7 * h7b.y;
    }
    return make_float4((a0.x + a1.x) + (a2.x + a3.x),
                       (a0.y + a1.y) + (a2.y + a3.y),
                       (a0.z + a1.z) + (a2.z + a3.z),
                       (a0.w + a1.w) + (a2.w + a3.w));
}

// ---------------- aggregation 1: conv1 + bias + BN + ELU -> bf16 split -------
__global__ __launch_bounds__(256) void k_agg1(const float* __restrict__ b0,
                       const float* __restrict__ gamma,
                       const float* __restrict__ beta,
                       const float* __restrict__ mean,
                       const float* __restrict__ var) {
    int lane = threadIdx.x & 31;
    int i = blockIdx.x * 8 + (threadIdx.x >> 5);   // 6250 * 8 = 50000 exact

    float4 acc = agg_gather_w(g_h2, i, lane);

    float4 bb = *(const float4*)(b0    + 4 * lane);
    float4 gm = *(const float4*)(gamma + 4 * lane);
    float4 bt = *(const float4*)(beta  + 4 * lane);
    float4 mn = *(const float4*)(mean  + 4 * lane);
    float4 vr = *(const float4*)(var   + 4 * lane);

    float y0 = (acc.x + bb.x - mn.x) * (gm.x * rsqrtf(vr.x + BN_EPS)) + bt.x;
    float y1 = (acc.y + bb.y - mn.y) * (gm.y * rsqrtf(vr.y + BN_EPS)) + bt.y;
    float y2 = (acc.z + bb.z - mn.z) * (gm.z * rsqrtf(vr.z + BN_EPS)) + bt.z;
    float y3 = (acc.w + bb.w - mn.w) * (gm.w * rsqrtf(vr.w + BN_EPS)) + bt.w;
    y0 = (y0 > 0.f) ? y0 : expm1f(y0);
    y1 = (y1 > 0.f) ? y1 : expm1f(y1);
    y2 = (y2 > 0.f) ? y2 : expm1f(y2);
    y3 = (y3 > 0.f) ? y3 : expm1f(y3);

    float h0 = __bfloat162float(__float2bfloat16(y0));
    float h1 = __bfloat162float(__float2bfloat16(y1));
    float h2 = __bfloat162float(__float2bfloat16(y2));
    float h3 = __bfloat162float(__float2bfloat16(y3));

    size_t o = (size_t)i * 64 + 2 * lane;   // bf162 index
    g_h1h2[o]     = __floats2bfloat162_rn(h0, h1);
    g_h1h2[o + 1] = __floats2bfloat162_rn(h2, h3);
    g_h1l2[o]     = __floats2bfloat162_rn(y0 - h0, y1 - h1);
    g_h1l2[o + 1] = __floats2bfloat162_rn(y2 - h2, y3 - h3);
}

// ---------------- aggregation 2 + final fusion mean --------------------------
__global__ __launch_bounds__(256) void k_agg2(const float* __restrict__ emb,
                       const float* __restrict__ b1,
                       float* __restrict__ out) {
    int lane = threadIdx.x & 31;
    int i = blockIdx.x * 8 + (threadIdx.x >> 5);

    float4 acc = agg_gather_w(g_g2, i, lane);

    float4 bb = *(const float4*)(b1 + 4 * lane);
    size_t o = (size_t)i * 128 + 4 * lane;
    float4 em = *(const float4*)(emb + o);

    size_t o2 = (size_t)i * 64 + 2 * lane;
    __nv_bfloat162 ha = g_h1h2[o2], hb = g_h1h2[o2 + 1];
    __nv_bfloat162 la = g_h1l2[o2], lb = g_h1l2[o2 + 1];
    float h1x = __bfloat162float(ha.x) + __bfloat162float(la.x);
    float h1y = __bfloat162float(ha.y) + __bfloat162float(la.y);
    float h1z = __bfloat162float(hb.x) + __bfloat162float(lb.x);
    float h1w = __bfloat162float(hb.y) + __bfloat162float(lb.y);

    float4 r;
    r.x = (em.x + h1x + acc.x + bb.x) * (1.0f / 3.0f);
    r.y = (em.y + h1y + acc.y + bb.y) * (1.0f / 3.0f);
    r.z = (em.z + h1z + acc.z + bb.z) * (1.0f / 3.0f);
    r.w = (em.w + h1w + acc.w + bb.w) * (1.0f / 3.0f);
    *(float4*)(out + o) = r;
}

// ---------------- launch: fork/join so GEMM1 overlaps graph prep -------------
extern "C" void kernel_launch(void* const* d_in, const int* in_sizes, int n_in,
                              void* d_out, int out_size) {
    const float* emb   = (const float*)d_in[0];
    const int*   ei    = (const int*)  d_in[1];
    const float* ew    = (const float*)d_in[2];
    const float* W0    = (const float*)d_in[3];
    const float* b0    = (const float*)d_in[4];
    const float* W1    = (const float*)d_in[5];
    const float* b1    = (const float*)d_in[6];
    const float* gamma = (const float*)d_in[7];
    const float* beta  = (const float*)d_in[8];
    const float* mean  = (const float*)d_in[9];
    const float* var   = (const float*)d_in[10];
    float* out = (float*)d_out;

    const int* row = ei;        // edge_index[0]
    const int* col = ei + EE;   // edge_index[1]

    const int NB_E = (EE + 255) / 256;
    const int NTILE = (NN + 127) / 128;   // 391

    // one-time handles (no device memory; identical work every call)
    static cudaStream_t s_side = ([]() {
        cudaStream_t t;
        cudaStreamCreateWithFlags(&t, cudaStreamNonBlocking);
        return t;
    })();
    static cudaEvent_t s_fork = ([]() {
        cudaEvent_t e;
        cudaEventCreateWithFlags(&e, cudaEventDisableTiming);
        return e;
    })();
    static cudaEvent_t s_join = ([]() {
        cudaEvent_t e;
        cudaEventCreateWithFlags(&e, cudaEventDisableTiming);
        return e;
    })();
    static bool s_attr = ([]() {
        cudaFuncSetAttribute(k_gemm_mma,
                             cudaFuncAttributeMaxDynamicSharedMemorySize, SM_TOT);
        return true;
    })();
    (void)s_attr;

    // fork: side branch = GEMM1 (independent of graph prep; splits W0 itself)
    cudaEventRecord(s_fork, 0);
    cudaStreamWaitEvent(s_side, s_fork, 0);
    k_gemm_mma<<<NTILE, 256, SM_TOT, s_side>>>(emb, W0, 0);   // g_h2 = emb @ W0
    cudaEventRecord(s_join, s_side);

    // main branch: graph norm + CSC build
    k_deg    <<<NB_E, 256>>>(col, ew);
    k_bsum   <<<NSCAN_BLK, 256>>>();
    k_scan3  <<<NSCAN_BLK, 256>>>();
    k_scatter<<<NB_E, 256>>>(row, col, ew);

    // join, then the dependent tail
    cudaStreamWaitEvent(0, s_join, 0);
    k_agg1<<<NN / 8, 256>>>(b0, gamma, beta, mean, var);
    k_gemm_mma<<<NTILE, 256, SM_TOT>>>(nullptr, W1, 1);       // g_g2 = h1 @ W1
    k_agg2<<<NN / 8, 256>>>(emb, b1, out);
}

// round 17
// speedup vs baseline: 1.1198x; 1.0171x over previous
#include <cuda_runtime.h>
#include <cuda_fp16.h>
#include <math.h>
#include <stdint.h>

#define NN 50000
#define EE 800000
#define DD 128
#define BN_EPS 1e-5f
#define NSCAN_BLK 196   // ceil(50000/256)

// ---------------- scratch (static device globals; no allocation) -------------
// Self-resetting protocol: g_pk and g_cnt start at 0 (BSS zero-init), are
// accumulated by k_deg, and are reset to 0 by their LAST reader each call.
__device__ unsigned long long g_pk[NN]; // packed: count<<40 | fix24(sum w)
__device__ float g_dis[NN];
__device__ int   g_cnt[NN];
__device__ int   g_off[NN];
__device__ int   g_cur[NN];
__device__ int   g_bsum[256];
__device__ int2  g_ed[EE];              // packed (src, weight-bits) per edge
__device__ __half2 g_h2[NN * 64];       // emb @ W0   (fp16, agg gather operand)
__device__ __half2 g_g2[NN * 64];       // h1 @ W1    (fp16, agg gather operand)
__device__ float g_h1[NN * DD];         // h1 (fp32, GEMM2 input)

// ---------------- small helpers ---------------------------------------------
__device__ __forceinline__ uint32_t f2tf(float x) {
    uint32_t r;
    asm("cvt.rna.tf32.f32 %0, %1;" : "=r"(r) : "f"(x));
    return r;
}

#define MMATF32(c, a0, a1, a2, a3, b0, b1) \
    asm volatile("mma.sync.aligned.m16n8k8.row.col.f32.tf32.tf32.f32 " \
                 "{%0,%1,%2,%3}, {%4,%5,%6,%7}, {%8,%9}, {%0,%1,%2,%3};" \
                 : "+f"((c)[0]), "+f"((c)[1]), "+f"((c)[2]), "+f"((c)[3]) \
                 : "r"(a0), "r"(a1), "r"(a2), "r"(a3), "r"(b0), "r"(b1))

// ---------------- norm + CSC build ------------------------------------------
// One packed 64-bit atomic per edge: count in bits [40..], weight sum as
// 24-bit fixed point in the low bits (w in [0,1), deg <= ~50 -> sum < 2^30).
__global__ void k_deg(const int* __restrict__ col, const float* __restrict__ w) {
    int e = blockIdx.x * blockDim.x + threadIdx.x;
    if (e < EE) {
        int c = col[e];
        unsigned long long inc = (1ULL << 40)
            + (unsigned long long)(w[e] * 16777216.0f);   // 2^24 fixed point
        atomicAdd(&g_pk[c], inc);
    }
}

// per-block sum of counts (scan level 1) + fused deg^-1/2 + g_pk reset
__global__ void k_bsum() {
    int i = blockIdx.x * 256 + threadIdx.x;
    int v = 0;
    if (i < NN) {
        unsigned long long pk = g_pk[i];
        v = (int)(pk >> 40);
        float deg = (float)(pk & ((1ULL << 40) - 1)) * (1.0f / 16777216.0f);
        g_dis[i] = rsqrtf(1.0f + deg);         // +1.0 = self-loop weight
        g_cnt[i] = v;
        g_pk[i] = 0ULL;                        // reset for next call
    }

#pragma unroll
    for (int o = 16; o > 0; o >>= 1) v += __shfl_down_sync(0xffffffffu, v, o);
    __shared__ int ws[8];
    int lane = threadIdx.x & 31, wid = threadIdx.x >> 5;
    if (lane == 0) ws[wid] = v;
    __syncthreads();
    if (threadIdx.x < 8) {
        int s = ws[threadIdx.x];
#pragma unroll
        for (int o = 4; o > 0; o >>= 1) s += __shfl_down_sync(0xffu, s, o);
        if (threadIdx.x == 0) g_bsum[blockIdx.x] = s;
    }
}

// scan level 2+3 fused: every block redundantly scans the 196 block sums in
// shared memory (cheap), then does its local scan; resets g_cnt.
__global__ void k_scan3() {
    __shared__ int bs[256];
    int t = threadIdx.x;
    bs[t] = (t < NSCAN_BLK) ? g_bsum[t] : 0;
    __syncthreads();
#pragma unroll
    for (int d = 1; d < 256; d <<= 1) {
        int u = (t >= d) ? bs[t - d] : 0;
        __syncthreads();
        bs[t] += u;
        __syncthreads();
    }
    int blk_base = (blockIdx.x == 0) ? 0 : bs[blockIdx.x - 1];

    int i = blockIdx.x * 256 + t;
    int v = (i < NN) ? g_cnt[i] : 0;
    int lane = t & 31, wid = t >> 5;

    int x = v;
#pragma unroll
    for (int o = 1; o < 32; o <<= 1) {
        int y = __shfl_up_sync(0xffffffffu, x, o);
        if (lane >= o) x += y;
    }
    __shared__ int wsum[8];
    if (lane == 31) wsum[wid] = x;
    __syncthreads();
    if (t < 8) {
        int s = wsum[t];
#pragma unroll
        for (int o = 1; o < 8; o <<= 1) {
            int y = __shfl_up_sync(0xffu, s, o);
            if (t >= o) s += y;
        }
        wsum[t] = s;
    }
    __syncthreads();
    int base = blk_base + ((wid > 0) ? wsum[wid - 1] : 0);
    int excl = base + x - v;
    if (i < NN) {
        g_off[i] = excl;
        g_cur[i] = excl;
        g_cnt[i] = 0;      // reset for next call (last reader)
    }
}

__global__ void k_scatter(const int* __restrict__ row, const int* __restrict__ col,
                          const float* __restrict__ w) {
    int e = blockIdx.x * blockDim.x + threadIdx.x;
    if (e < EE) {
        int r = row[e], c = col[e];
        int p = atomicAdd(&g_cur[c], 1);
        float wn = g_dis[r] * w[e] * g_dis[c];
        g_ed[p] = make_int2(r, __float_as_int(wn));   // one 8B scattered store
    }
}

// =============== tensor-core GEMM: single-pass TF32 m16n8k8 ==================
// C[128tile,128] = A @ W, fp32 accumulate, fp16 output.
// SMEM pitch 136 floats -> P mod 32 = 8 -> B fragment loads conflict-free.
#define P32 136
#define MATF_BYTES (128 * P32 * 4)     // 69632
#define SM_TOT (2 * MATF_BYTES)        // 139264

__global__ __launch_bounds__(256) void k_gemm_tf32(const float* __restrict__ Af,
                                                   const float* __restrict__ W,
                                                   int sel) {
    extern __shared__ __align__(16) char sm[];
    uint32_t* As = (uint32_t*)(sm);                 // tf32 bits
    uint32_t* Ws = (uint32_t*)(sm + MATF_BYTES);

    __half2* C2 = (sel == 0) ? g_h2 : g_g2;
    const float* A = (sel == 0) ? Af : g_h1;

    int tid = threadIdx.x;
    int lane = tid & 31, wid = tid >> 5;
    int rowBase = blockIdx.x * 128;

    // ---- stage W tile (fp32 -> tf32 bits), float4-coalesced
#pragma unroll
    for (int it = 0; it < 16; it++) {
        int idx = tid + it * 256;            // 0..4095 float4s
        int k = idx >> 5, n = (idx & 31) * 4;
        float4 v = *(const float4*)(W + k * 128 + n);
        uint4 u = make_uint4(f2tf(v.x), f2tf(v.y), f2tf(v.z), f2tf(v.w));
        *(uint4*)(Ws + k * P32 + n) = u;
    }
    // ---- stage A tile
#pragma unroll
    for (int it = 0; it < 16; it++) {
        int idx = tid + it * 256;            // 0..4095 float4s
        int r = idx >> 5, c = (idx & 31) * 4;
        int gr = rowBase + r;
        float4 v = (gr < NN) ? *(const float4*)(A + (size_t)gr * 128 + c)
                             : make_float4(0.f, 0.f, 0.f, 0.f);
        uint4 u = make_uint4(f2tf(v.x), f2tf(v.y), f2tf(v.z), f2tf(v.w));
        *(uint4*)(As + r * P32 + c) = u;
    }
    __syncthreads();

    int m0 = (wid & 3) * 32;
    int n0 = (wid >> 2) * 64;
    int g = lane >> 2, t = lane & 3;

    float acc[2][8][4];
#pragma unroll
    for (int mt = 0; mt < 2; mt++)
#pragma unroll
        for (int j = 0; j < 8; j++)
#pragma unroll
            for (int q = 0; q < 4; q++) acc[mt][j][q] = 0.f;

#pragma unroll
    for (int ks = 0; ks < 16; ks++) {
        int k0 = ks * 8;
        uint32_t a[2][4];
#pragma unroll
        for (int mt = 0; mt < 2; mt++) {
            int r0 = m0 + mt * 16 + g;
            a[mt][0] = As[r0 * P32 + k0 + t];
            a[mt][1] = As[(r0 + 8) * P32 + k0 + t];
            a[mt][2] = As[r0 * P32 + k0 + t + 4];
            a[mt][3] = As[(r0 + 8) * P32 + k0 + t + 4];
        }
#pragma unroll
        for (int j = 0; j < 8; j++) {
            uint32_t b0 = Ws[(k0 + t) * P32 + n0 + j * 8 + g];
            uint32_t b1 = Ws[(k0 + t + 4) * P32 + n0 + j * 8 + g];
            MMATF32(acc[0][j], a[0][0], a[0][1], a[0][2], a[0][3], b0, b1);
            MMATF32(acc[1][j], a[1][0], a[1][1], a[1][2], a[1][3], b0, b1);
        }
    }

    // ---- epilogue: native __half2 stores (cc even -> n even)
    int rr = g, cc = t * 2;
#pragma unroll
    for (int mt = 0; mt < 2; mt++) {
        int r0 = rowBase + m0 + mt * 16 + rr;
        bool v0 = r0 < NN, v1 = (r0 + 8) < NN;
#pragma unroll
        for (int j = 0; j < 8; j++) {
            int n2 = (n0 + j * 8 + cc) >> 1;
            if (v0) C2[(size_t)r0 * 64 + n2]
                        = __floats2half2_rn(acc[mt][j][0], acc[mt][j][1]);
            if (v1) C2[(size_t)(r0 + 8) * 64 + n2]
                        = __floats2half2_rn(acc[mt][j][2], acc[mt][j][3]);
        }
    }
}

// ======= aggregation core: ONE WARP per node, half2 lanes, unroll 8 ==========
// lane owns features [4*lane, 4*lane+4) = half2 elements {2*lane, 2*lane+1}.
__device__ __forceinline__ float4 agg_gather_w(const __half2* __restrict__ H2,
                                               int i, int lane) {
    float di = g_dis[i];
    float sw = di * di;
    size_t sb = (size_t)i * 64 + 2 * lane;
    float2 sa = __half22float2(H2[sb]);
    float2 sc = __half22float2(H2[sb + 1]);
    float4 a0 = make_float4(sw * sa.x, sw * sa.y, sw * sc.x, sw * sc.y);
    float4 a1 = make_float4(0.f, 0.f, 0.f, 0.f);
    float4 a2 = a1, a3 = a1;

    int s = g_off[i];
    int n = ((i + 1 < NN) ? g_off[i + 1] : EE) - s;
    const int2 zz = make_int2(0, 0);

    for (int p = 0; p < n; p += 8) {
        bool u1 = p + 1 < n, u2 = p + 2 < n, u3 = p + 3 < n;
        bool u4 = p + 4 < n, u5 = p + 5 < n, u6 = p + 6 < n, u7 = p + 7 < n;
        int2 e0 = g_ed[s + p];
        int2 e1 = u1 ? g_ed[s + p + 1] : zz;
        int2 e2 = u2 ? g_ed[s + p + 2] : zz;
        int2 e3 = u3 ? g_ed[s + p + 3] : zz;
        int2 e4 = u4 ? g_ed[s + p + 4] : zz;
        int2 e5 = u5 ? g_ed[s + p + 5] : zz;
        int2 e6 = u6 ? g_ed[s + p + 6] : zz;
        int2 e7 = u7 ? g_ed[s + p + 7] : zz;

        float w0 = __int_as_float(e0.y), w1 = __int_as_float(e1.y);
        float w2 = __int_as_float(e2.y), w3 = __int_as_float(e3.y);
        float w4 = __int_as_float(e4.y), w5 = __int_as_float(e5.y);
        float w6 = __int_as_float(e6.y), w7 = __int_as_float(e7.y);

        size_t b0 = (size_t)e0.x * 64 + 2 * lane;
        size_t b1 = (size_t)e1.x * 64 + 2 * lane;
        size_t b2 = (size_t)e2.x * 64 + 2 * lane;
        size_t b3 = (size_t)e3.x * 64 + 2 * lane;
        size_t b4 = (size_t)e4.x * 64 + 2 * lane;
        size_t b5 = (size_t)e5.x * 64 + 2 * lane;
        size_t b6 = (size_t)e6.x * 64 + 2 * lane;
        size_t b7 = (size_t)e7.x * 64 + 2 * lane;
        float2 h0a = __half22float2(H2[b0]), h0b = __half22float2(H2[b0 + 1]);
        float2 h1a = __half22float2(H2[b1]), h1b = __half22float2(H2[b1 + 1]);
        float2 h2a = __half22float2(H2[b2]), h2b = __half22float2(H2[b2 + 1]);
        float2 h3a = __half22float2(H2[b3]), h3b = __half22float2(H2[b3 + 1]);
        float2 h4a = __half22float2(H2[b4]), h4b = __half22float2(H2[b4 + 1]);
        float2 h5a = __half22float2(H2[b5]), h5b = __half22float2(H2[b5 + 1]);
        float2 h6a = __half22float2(H2[b6]), h6b = __half22float2(H2[b6 + 1]);
        float2 h7a = __half22float2(H2[b7]), h7b = __half22float2(H2[b7 + 1]);

        a0.x += w0 * h0a.x; a0.y += w0 * h0a.y; a0.z += w0 * h0b.x; a0.w += w0 * h0b.y;
        a1.x += w1 * h1a.x; a1.y += w1 * h1a.y; a1.z += w1 * h1b.x; a1.w += w1 * h1b.y;
        a2.x += w2 * h2a.x; a2.y += w2 * h2a.y; a2.z += w2 * h2b.x; a2.w += w2 * h2b.y;
        a3.x += w3 * h3a.x; a3.y += w3 * h3a.y; a3.z += w3 * h3b.x; a3.w += w3 * h3b.y;
        a0.x += w4 * h4a.x; a0.y += w4 * h4a.y; a0.z += w4 * h4b.x; a0.w += w4 * h4b.y;
        a1.x += w5 * h5a.x; a1.y += w5 * h5a.y; a1.z += w5 * h5b.x; a1.w += w5 * h5b.y;
        a2.x += w6 * h6a.x; a2.y += w6 * h6a.y; a2.z += w6 * h6b.x; a2.w += w6 * h6b.y;
        a3.x += w7 * h7a.x; a3.y += w7 * h7a.y; a3.z += w7 * h7b.x; a3.w += w7 * h7b.y;
    }
    return make_float4((a0.x + a1.x) + (a2.x + a3.x),
                       (a0.y + a1.y) + (a2.y + a3.y),
                       (a0.z + a1.z) + (a2.z + a3.z),
                       (a0.w + a1.w) + (a2.w + a3.w));
}

// ---------------- aggregation 1: conv1 + bias + BN + ELU -> fp32 h1 ----------
__global__ __launch_bounds__(256) void k_agg1(const float* __restrict__ b0,
                       const float* __restrict__ gamma,
                       const float* __restrict__ beta,
                       const float* __restrict__ mean,
                       const float* __restrict__ var) {
    int lane = threadIdx.x & 31;
    int i = blockIdx.x * 8 + (threadIdx.x >> 5);   // 6250 * 8 = 50000 exact

    float4 acc = agg_gather_w(g_h2, i, lane);

    float4 bb = *(const float4*)(b0    + 4 * lane);
    float4 gm = *(const float4*)(gamma + 4 * lane);
    float4 bt = *(const float4*)(beta  + 4 * lane);
    float4 mn = *(const float4*)(mean  + 4 * lane);
    float4 vr = *(const float4*)(var   + 4 * lane);

    float y0 = (acc.x + bb.x - mn.x) * (gm.x * rsqrtf(vr.x + BN_EPS)) + bt.x;
    float y1 = (acc.y + bb.y - mn.y) * (gm.y * rsqrtf(vr.y + BN_EPS)) + bt.y;
    float y2 = (acc.z + bb.z - mn.z) * (gm.z * rsqrtf(vr.z + BN_EPS)) + bt.z;
    float y3 = (acc.w + bb.w - mn.w) * (gm.w * rsqrtf(vr.w + BN_EPS)) + bt.w;
    y0 = (y0 > 0.f) ? y0 : expm1f(y0);
    y1 = (y1 > 0.f) ? y1 : expm1f(y1);
    y2 = (y2 > 0.f) ? y2 : expm1f(y2);
    y3 = (y3 > 0.f) ? y3 : expm1f(y3);

    *(float4*)(g_h1 + (size_t)i * 128 + 4 * lane) = make_float4(y0, y1, y2, y3);
}

// ---------------- aggregation 2 + final fusion mean --------------------------
__global__ __launch_bounds__(256) void k_agg2(const float* __restrict__ emb,
                       const float* __restrict__ b1,
                       float* __restrict__ out) {
    int lane = threadIdx.x & 31;
    int i = blockIdx.x * 8 + (threadIdx.x >> 5);

    float4 acc = agg_gather_w(g_g2, i, lane);

    float4 bb = *(const float4*)(b1 + 4 * lane);
    size_t o = (size_t)i * 128 + 4 * lane;
    float4 em = *(const float4*)(emb + o);
    float4 h1 = *(const float4*)(g_h1 + o);

    float4 r;
    r.x = (em.x + h1.x + acc.x + bb.x) * (1.0f / 3.0f);
    r.y = (em.y + h1.y + acc.y + bb.y) * (1.0f / 3.0f);
    r.z = (em.z + h1.z + acc.z + bb.z) * (1.0f / 3.0f);
    r.w = (em.w + h1.w + acc.w + bb.w) * (1.0f / 3.0f);
    *(float4*)(out + o) = r;
}

// ---------------- launch: fork/join so GEMM1 overlaps graph prep -------------
extern "C" void kernel_launch(void* const* d_in, const int* in_sizes, int n_in,
                              void* d_out, int out_size) {
    const float* emb   = (const float*)d_in[0];
    const int*   ei    = (const int*)  d_in[1];
    const float* ew    = (const float*)d_in[2];
    const float* W0    = (const float*)d_in[3];
    const float* b0    = (const float*)d_in[4];
    const float* W1    = (const float*)d_in[5];
    const float* b1    = (const float*)d_in[6];
    const float* gamma = (const float*)d_in[7];
    const float* beta  = (const float*)d_in[8];
    const float* mean  = (const float*)d_in[9];
    const float* var   = (const float*)d_in[10];
    float* out = (float*)d_out;

    const int* row = ei;        // edge_index[0]
    const int* col = ei + EE;   // edge_index[1]

    const int NB_E = (EE + 255) / 256;
    const int NTILE = (NN + 127) / 128;   // 391

    // one-time handles (no device memory; identical work every call)
    static cudaStream_t s_side = ([]() {
        cudaStream_t t;
        cudaStreamCreateWithFlags(&t, cudaStreamNonBlocking);
        return t;
    })();
    static cudaEvent_t s_fork = ([]() {
        cudaEvent_t e;
        cudaEventCreateWithFlags(&e, cudaEventDisableTiming);
        return e;
    })();
    static cudaEvent_t s_join = ([]() {
        cudaEvent_t e;
        cudaEventCreateWithFlags(&e, cudaEventDisableTiming);
        return e;
    })();
    static bool s_attr = ([]() {
        cudaFuncSetAttribute(k_gemm_tf32,
                             cudaFuncAttributeMaxDynamicSharedMemorySize, SM_TOT);
        return true;
    })();
    (void)s_attr;

    // fork: side branch = GEMM1 (independent of graph prep)
    cudaEventRecord(s_fork, 0);
    cudaStreamWaitEvent(s_side, s_fork, 0);
    k_gemm_tf32<<<NTILE, 256, SM_TOT, s_side>>>(emb, W0, 0);  // g_h2 = emb @ W0
    cudaEventRecord(s_join, s_side);

    // main branch: graph norm + CSC build
    k_deg    <<<NB_E, 256>>>(col, ew);
    k_bsum   <<<NSCAN_BLK, 256>>>();
    k_scan3  <<<NSCAN_BLK, 256>>>();
    k_scatter<<<NB_E, 256>>>(row, col, ew);

    // join, then the dependent tail
    cudaStreamWaitEvent(0, s_join, 0);
    k_agg1<<<NN / 8, 256>>>(b0, gamma, beta, mean, var);
    k_gemm_tf32<<<NTILE, 256, SM_TOT>>>(nullptr, W1, 1);      // g_g2 = h1 @ W1
    k_agg2<<<NN / 8, 256>>>(emb, b1, out);
}